// round 12
// baseline (speedup 1.0000x reference)
#include <cuda_runtime.h>
#include <cstdint>

#define N_NODES  50000
#define N_EDGES  800000
#define IN_CH    128
#define HID      64
#define N_GRAPHS 512
#define OUT_CH   10

#define TILE_ROWS 64
#define NTHREADS  128
#define SX_STRIDE 68                    // 272B row stride: 16B-aligned, conflict-free
#define SMEM_BYTES (TILE_ROWS * SX_STRIDE * 4 + 64 * 64 * 4)   // 33792

// ---------------- scratch (static device memory; no allocations) ------------
__device__ float g_bufA[N_NODES * HID];   // y (pre-agg features)
__device__ float g_bufB[N_NODES * HID];   // agg buffer (atomics target)
__device__ float g_bufC[N_NODES * HID];   // h0
__device__ float g_pooled[N_GRAPHS * HID];

// ---------------- packed f32x2 helpers --------------------------------------
#define FMA2(acc, a, b) \
    asm("fma.rn.f32x2 %0, %1, %2, %0;" : "+l"(acc) : "l"(a), "l"(b))
#define PACK2(out, x) \
    asm("mov.b64 %0, {%1, %1};" : "=l"(out) : "r"(__float_as_uint(x)))
#define UNPACK2(lo, hi, in) \
    asm("mov.b64 {%0, %1}, %2;" : "=r"(lo), "=r"(hi) : "l"(in))

// ============================================================================
// Shared GEMM core (64x64 tile, 128 threads, 4 rows x 8 cols per thread,
// f32x2 accumulators; each x element packed ONCE and reused for 4 FMA2s)
// Thread t: cols [tc*8, tc*8+8), rows {tr + 16*i}, tc = t&7, tr = t>>3 (0..15).
// ============================================================================

#define GEMM_ACC_DECL  unsigned long long acc[4][4] = {}

#define GEMM_COMPUTE_CHUNK(sX, sW)                                            \
    _Pragma("unroll 4")                                                       \
    for (int k = 0; k < 64; k += 4) {                                         \
        _Pragma("unroll")                                                     \
        for (int kk = 0; kk < 4; ++kk) {                                      \
            ulonglong2 wa = *(const ulonglong2*)&sW[(k + kk) * 64 + tc * 8];  \
            ulonglong2 wb = *(const ulonglong2*)&sW[(k + kk) * 64 + tc * 8 + 4]; \
            _Pragma("unroll")                                                 \
            for (int i = 0; i < 4; ++i) {                                     \
                float xv = sX[(tr + 16 * i) * SX_STRIDE + k + kk];            \
                unsigned long long xx;                                        \
                PACK2(xx, xv);                                                \
                FMA2(acc[i][0], xx, wa.x); FMA2(acc[i][1], xx, wa.y);         \
                FMA2(acc[i][2], xx, wb.x); FMA2(acc[i][3], xx, wb.y);         \
            }                                                                 \
        }                                                                     \
    }

// unpack row i's 8 accumulated columns into float4 o0 (cols 0-3), o1 (cols 4-7)
#define GEMM_UNPACK_ROW(i, o0, o1)                                            \
    {                                                                         \
        unsigned int u0, u1, u2, u3, u4, u5, u6, u7;                          \
        UNPACK2(u0, u1, acc[i][0]); UNPACK2(u2, u3, acc[i][1]);               \
        UNPACK2(u4, u5, acc[i][2]); UNPACK2(u6, u7, acc[i][3]);               \
        o0.x = __uint_as_float(u0); o0.y = __uint_as_float(u1);               \
        o0.z = __uint_as_float(u2); o0.w = __uint_as_float(u3);               \
        o1.x = __uint_as_float(u4); o1.y = __uint_as_float(u5);               \
        o1.z = __uint_as_float(u6); o1.w = __uint_as_float(u7);               \
    }

// load 64x64 W chunk (row-major, contiguous) into sW via float4
#define LOAD_W_CHUNK(sW, Wptr)                                                \
    _Pragma("unroll")                                                         \
    for (int i = 0; i < 8; ++i) {                                             \
        int f4 = tid + i * NTHREADS;       /* 1024 float4s */                 \
        *(float4*)&sW[f4 * 4] = *(const float4*)&(Wptr)[f4 * 4];              \
    }

// epilogue: relu(acc + bias) and store 8 cols for rows tr+16i
#define GEMM_EPILOGUE_RELU(outp, bias)                                        \
    {                                                                         \
        const float4 bv0 = *(const float4*)&(bias)[tc * 8];                   \
        const float4 bv1 = *(const float4*)&(bias)[tc * 8 + 4];               \
        _Pragma("unroll")                                                     \
        for (int i = 0; i < 4; ++i) {                                         \
            int row = row0 + tr + 16 * i;                                     \
            if (row < N_NODES) {                                              \
                float4 o0, o1;                                                \
                GEMM_UNPACK_ROW(i, o0, o1)                                    \
                o0.x = fmaxf(o0.x + bv0.x, 0.f); o0.y = fmaxf(o0.y + bv0.y, 0.f); \
                o0.z = fmaxf(o0.z + bv0.z, 0.f); o0.w = fmaxf(o0.w + bv0.w, 0.f); \
                o1.x = fmaxf(o1.x + bv1.x, 0.f); o1.y = fmaxf(o1.y + bv1.y, 0.f); \
                o1.z = fmaxf(o1.z + bv1.z, 0.f); o1.w = fmaxf(o1.w + bv1.w, 0.f); \
                *(float4*)&(outp)[(size_t)row * 64 + tc * 8] = o0;            \
                *(float4*)&(outp)[(size_t)row * 64 + tc * 8 + 4] = o1;        \
            }                                                                 \
        }                                                                     \
    }

// ============================================================================
// K1: y0 = x @ w0a  (K=128). Tail: zero agg rows; block 0 zeroes pooled.
// ============================================================================
__global__ void __launch_bounds__(NTHREADS, 6) gemm_in_kernel(
    const float* __restrict__ A, const float* __restrict__ W,
    float* __restrict__ out, float* __restrict__ aggz, float* __restrict__ pooled)
{
    extern __shared__ float smem[];
    float* sX = smem;
    float* sW = smem + TILE_ROWS * SX_STRIDE;

    const int tid = threadIdx.x;
    const int tc = tid & 7;
    const int tr = tid >> 3;
    const int row0 = blockIdx.x * TILE_ROWS;

    GEMM_ACC_DECL;

    for (int kc = 0; kc < IN_CH; kc += 64) {
        LOAD_W_CHUNK(sW, W + kc * 64)
#pragma unroll
        for (int i = 0; i < 8; ++i) {
            int f4 = tid + i * NTHREADS;       // 1024 float4s = 64 rows x 16
            int r = f4 >> 4, c4 = f4 & 15;
            int row = row0 + r;
            float4 v = make_float4(0.f, 0.f, 0.f, 0.f);
            if (row < N_NODES)
                v = *(const float4*)&A[(size_t)row * IN_CH + kc + c4 * 4];
            *(float4*)&sX[r * SX_STRIDE + c4 * 4] = v;
        }
        __syncthreads();
        GEMM_COMPUTE_CHUNK(sX, sW)
        __syncthreads();
    }

#pragma unroll
    for (int i = 0; i < 4; ++i) {
        int row = row0 + tr + 16 * i;
        if (row < N_NODES) {
            float4 o0, o1;
            GEMM_UNPACK_ROW(i, o0, o1)
            *(float4*)&out[(size_t)row * 64 + tc * 8] = o0;
            *(float4*)&out[(size_t)row * 64 + tc * 8 + 4] = o1;
        }
    }

    const float4 z4 = make_float4(0.f, 0.f, 0.f, 0.f);
#pragma unroll
    for (int i = 0; i < 8; ++i) {
        int f4 = tid + i * NTHREADS;
        int row = row0 + (f4 >> 4);
        if (row < N_NODES)
            *(float4*)&aggz[(size_t)row * 64 + (f4 & 15) * 4] = z4;
    }
    if (blockIdx.x == 0) {
        for (int i = tid; i < N_GRAPHS * HID / 4; i += NTHREADS)
            ((float4*)pooled)[i] = z4;
    }
}

// ============================================================================
// Edge aggregation (8 edges/thread, red.global.add.v4) — proven kernel.
// ============================================================================
#define E_PER 8
__global__ void __launch_bounds__(256) edge_agg_kernel(
    const float* __restrict__ y, const int* __restrict__ ei,
    float* __restrict__ agg)
{
    const int t = blockIdx.x * blockDim.x + threadIdx.x;
    const int c4 = t & 15;
    const int eb = (t >> 4) * E_PER;
    if (eb >= N_EDGES) return;

    int s[E_PER], d[E_PER];
#pragma unroll
    for (int j = 0; j < E_PER; ++j) {
        s[j] = __ldg(&ei[eb + j]);
        d[j] = __ldg(&ei[N_EDGES + eb + j]);
    }
    float4 v[E_PER];
#pragma unroll
    for (int j = 0; j < E_PER; ++j)
        v[j] = *(const float4*)(y + (size_t)s[j] * 64 + c4 * 4);
#pragma unroll
    for (int j = 0; j < E_PER; ++j) {
        float* p = agg + (size_t)d[j] * 64 + c4 * 4;
        asm volatile("red.global.add.v4.f32 [%0], {%1,%2,%3,%4};"
                     :: "l"(p), "f"(v[j].x), "f"(v[j].y), "f"(v[j].z), "f"(v[j].w)
                     : "memory");
    }
}

// ============================================================================
// K3: combine + GEMM:  out = relu( relu((1+eps)*A + G + preb) @ W + bias )
//     Also zeroes G behind the read (prepares bufB for layer-1 atomics).
// ============================================================================
__global__ void __launch_bounds__(NTHREADS, 6) combine_gemm_kernel(
    const float* __restrict__ A, float* __restrict__ G,
    const float* __restrict__ epsp, const float* __restrict__ preb,
    const float* __restrict__ W, const float* __restrict__ bias,
    float* __restrict__ out)
{
    extern __shared__ float smem[];
    float* sX = smem;
    float* sW = smem + TILE_ROWS * SX_STRIDE;

    const int tid = threadIdx.x;
    const int tc = tid & 7;
    const int tr = tid >> 3;
    const int row0 = blockIdx.x * TILE_ROWS;
    const float epsf = 1.0f + __ldg(&epsp[0]);
    const float4 z4 = make_float4(0.f, 0.f, 0.f, 0.f);

    LOAD_W_CHUNK(sW, W)
#pragma unroll
    for (int i = 0; i < 8; ++i) {
        int f4 = tid + i * NTHREADS;
        int r = f4 >> 4, c4 = f4 & 15;
        int row = row0 + r;
        float4 v = make_float4(0.f, 0.f, 0.f, 0.f);
        if (row < N_NODES) {
            size_t off = (size_t)row * 64 + c4 * 4;
            float4 a = *(const float4*)&A[off];
            float4 g = *(const float4*)&G[off];
            float4 pb = *(const float4*)&preb[c4 * 4];
            v.x = fmaxf(fmaf(epsf, a.x, g.x) + pb.x, 0.f);
            v.y = fmaxf(fmaf(epsf, a.y, g.y) + pb.y, 0.f);
            v.z = fmaxf(fmaf(epsf, a.z, g.z) + pb.z, 0.f);
            v.w = fmaxf(fmaf(epsf, a.w, g.w) + pb.w, 0.f);
            *(float4*)&G[off] = z4;          // re-zero for layer-1 aggregation
        }
        *(float4*)&sX[r * SX_STRIDE + c4 * 4] = v;
    }
    __syncthreads();

    GEMM_ACC_DECL;
    GEMM_COMPUTE_CHUNK(sX, sW)
    GEMM_EPILOGUE_RELU(out, bias)
}

// ============================================================================
// K4: pure GEMM: out = A @ W   (no tail work)
// ============================================================================
__global__ void __launch_bounds__(NTHREADS, 6) gemm64_kernel(
    const float* __restrict__ A, const float* __restrict__ W,
    float* __restrict__ out)
{
    extern __shared__ float smem[];
    float* sX = smem;
    float* sW = smem + TILE_ROWS * SX_STRIDE;

    const int tid = threadIdx.x;
    const int tc = tid & 7;
    const int tr = tid >> 3;
    const int row0 = blockIdx.x * TILE_ROWS;

    LOAD_W_CHUNK(sW, W)
#pragma unroll
    for (int i = 0; i < 8; ++i) {
        int f4 = tid + i * NTHREADS;
        int r = f4 >> 4, c4 = f4 & 15;
        int row = row0 + r;
        float4 v = make_float4(0.f, 0.f, 0.f, 0.f);
        if (row < N_NODES)
            v = *(const float4*)&A[(size_t)row * 64 + c4 * 4];
        *(float4*)&sX[r * SX_STRIDE + c4 * 4] = v;
    }
    __syncthreads();

    GEMM_ACC_DECL;
    GEMM_COMPUTE_CHUNK(sX, sW)

#pragma unroll
    for (int i = 0; i < 4; ++i) {
        int row = row0 + tr + 16 * i;
        if (row < N_NODES) {
            float4 o0, o1;
            GEMM_UNPACK_ROW(i, o0, o1)
            *(float4*)&out[(size_t)row * 64 + tc * 8] = o0;
            *(float4*)&out[(size_t)row * 64 + tc * 8 + 4] = o1;
        }
    }
}

// ============================================================================
// K6: combine + GEMM + pool (h1 never hits global)
// ============================================================================
__global__ void __launch_bounds__(NTHREADS, 6) combine_gemm_pool_kernel(
    const float* __restrict__ A, const float* __restrict__ G,
    const float* __restrict__ epsp, const float* __restrict__ preb,
    const float* __restrict__ W, const float* __restrict__ bias,
    const int* __restrict__ batch, float* __restrict__ pooled)
{
    extern __shared__ float smem[];
    float* sX = smem;
    float* sW = smem + TILE_ROWS * SX_STRIDE;

    const int tid = threadIdx.x;
    const int tc = tid & 7;
    const int tr = tid >> 3;
    const int row0 = blockIdx.x * TILE_ROWS;
    const float epsf = 1.0f + __ldg(&epsp[0]);

    LOAD_W_CHUNK(sW, W)
#pragma unroll
    for (int i = 0; i < 8; ++i) {
        int f4 = tid + i * NTHREADS;
        int r = f4 >> 4, c4 = f4 & 15;
        int row = row0 + r;
        float4 v = make_float4(0.f, 0.f, 0.f, 0.f);
        if (row < N_NODES) {
            size_t off = (size_t)row * 64 + c4 * 4;
            float4 a = *(const float4*)&A[off];
            float4 g = *(const float4*)&G[off];
            float4 pb = *(const float4*)&preb[c4 * 4];
            v.x = fmaxf(fmaf(epsf, a.x, g.x) + pb.x, 0.f);
            v.y = fmaxf(fmaf(epsf, a.y, g.y) + pb.y, 0.f);
            v.z = fmaxf(fmaf(epsf, a.z, g.z) + pb.z, 0.f);
            v.w = fmaxf(fmaf(epsf, a.w, g.w) + pb.w, 0.f);
        }
        *(float4*)&sX[r * SX_STRIDE + c4 * 4] = v;
    }
    __syncthreads();

    GEMM_ACC_DECL;
    GEMM_COMPUTE_CHUNK(sX, sW)

    const float4 bv0 = *(const float4*)&bias[tc * 8];
    const float4 bv1 = *(const float4*)&bias[tc * 8 + 4];
#pragma unroll
    for (int i = 0; i < 4; ++i) {
        int row = row0 + tr + 16 * i;
        if (row < N_NODES) {
            int g = __ldg(&batch[row]);
            float4 o0, o1;
            GEMM_UNPACK_ROW(i, o0, o1)
            o0.x = fmaxf(o0.x + bv0.x, 0.f); o0.y = fmaxf(o0.y + bv0.y, 0.f);
            o0.z = fmaxf(o0.z + bv0.z, 0.f); o0.w = fmaxf(o0.w + bv0.w, 0.f);
            o1.x = fmaxf(o1.x + bv1.x, 0.f); o1.y = fmaxf(o1.y + bv1.y, 0.f);
            o1.z = fmaxf(o1.z + bv1.z, 0.f); o1.w = fmaxf(o1.w + bv1.w, 0.f);
            float* p0 = pooled + (size_t)g * 64 + tc * 8;
            asm volatile("red.global.add.v4.f32 [%0], {%1,%2,%3,%4};"
                         :: "l"(p0), "f"(o0.x), "f"(o0.y), "f"(o0.z), "f"(o0.w) : "memory");
            asm volatile("red.global.add.v4.f32 [%0], {%1,%2,%3,%4};"
                         :: "l"(p0 + 4), "f"(o1.x), "f"(o1.y), "f"(o1.z), "f"(o1.w) : "memory");
        }
    }
}

// ============================================================================
// K7: head: logits + log_softmax
// ============================================================================
__global__ void __launch_bounds__(256) head_kernel(
    const float* __restrict__ pooled, const float* __restrict__ fcw,
    const float* __restrict__ fcb, float* __restrict__ out)
{
    int g = blockIdx.x * blockDim.x + threadIdx.x;
    if (g >= N_GRAPHS) return;
    float logit[OUT_CH];
#pragma unroll
    for (int j = 0; j < OUT_CH; ++j) logit[j] = __ldg(&fcb[j]);
#pragma unroll 8
    for (int k = 0; k < HID; ++k) {
        float p = pooled[g * HID + k];
#pragma unroll
        for (int j = 0; j < OUT_CH; ++j)
            logit[j] += p * __ldg(&fcw[k * OUT_CH + j]);
    }
    float m = logit[0];
#pragma unroll
    for (int j = 1; j < OUT_CH; ++j) m = fmaxf(m, logit[j]);
    float s = 0.f;
#pragma unroll
    for (int j = 0; j < OUT_CH; ++j) s += __expf(logit[j] - m);
    float ls = m + logf(s);
#pragma unroll
    for (int j = 0; j < OUT_CH; ++j) out[g * OUT_CH + j] = logit[j] - ls;
}

// ---------------- launch ----------------------------------------------------
extern "C" void kernel_launch(void* const* d_in, const int* in_sizes, int n_in,
                              void* d_out, int out_size)
{
    const float* x    = (const float*)d_in[0];
    const int*   ei   = (const int*)d_in[1];
    const int*   batch= (const int*)d_in[2];
    const float* eps0 = (const float*)d_in[3];
    const float* w0a  = (const float*)d_in[4];
    const float* b0a  = (const float*)d_in[5];
    const float* w0b  = (const float*)d_in[6];
    const float* b0b  = (const float*)d_in[7];
    const float* eps1 = (const float*)d_in[8];
    const float* w1a  = (const float*)d_in[9];
    const float* b1a  = (const float*)d_in[10];
    const float* w1b  = (const float*)d_in[11];
    const float* b1b  = (const float*)d_in[12];
    const float* fcw  = (const float*)d_in[13];
    const float* fcb  = (const float*)d_in[14];
    float*       out  = (float*)d_out;

    float *bufA, *bufB, *bufC, *pooled;
    cudaGetSymbolAddress((void**)&bufA, g_bufA);
    cudaGetSymbolAddress((void**)&bufB, g_bufB);
    cudaGetSymbolAddress((void**)&bufC, g_bufC);
    cudaGetSymbolAddress((void**)&pooled, g_pooled);

    static bool attr_done = false;
    if (!attr_done) {
        cudaFuncSetAttribute(gemm_in_kernel,
            cudaFuncAttributeMaxDynamicSharedMemorySize, SMEM_BYTES);
        cudaFuncSetAttribute(combine_gemm_kernel,
            cudaFuncAttributeMaxDynamicSharedMemorySize, SMEM_BYTES);
        cudaFuncSetAttribute(gemm64_kernel,
            cudaFuncAttributeMaxDynamicSharedMemorySize, SMEM_BYTES);
        cudaFuncSetAttribute(combine_gemm_pool_kernel,
            cudaFuncAttributeMaxDynamicSharedMemorySize, SMEM_BYTES);
        attr_done = true;
    }

    const int gemm_blocks = (N_NODES + TILE_ROWS - 1) / TILE_ROWS;   // 782
    const int edge_blocks = (N_EDGES / E_PER * 16 + 255) / 256;      // 6250

    // K1: y0 = x @ w0a ; zero bufB + pooled
    gemm_in_kernel<<<gemm_blocks, NTHREADS, SMEM_BYTES>>>(x, w0a, bufA, bufB, pooled);
    // K2: agg0 = scatter-add(y0)
    edge_agg_kernel<<<edge_blocks, 256>>>(bufA, ei, bufB);
    // K3: h0 = relu(relu(combine0) @ w0b + b0b) ; re-zero bufB behind the read
    combine_gemm_kernel<<<gemm_blocks, NTHREADS, SMEM_BYTES>>>(bufA, bufB, eps0, b0a, w0b, b0b, bufC);
    // K4: y1 = h0 @ w1a  (pure GEMM)
    gemm64_kernel<<<gemm_blocks, NTHREADS, SMEM_BYTES>>>(bufC, w1a, bufA);
    // K5: agg1 = scatter-add(y1)
    edge_agg_kernel<<<edge_blocks, 256>>>(bufA, ei, bufB);
    // K6: h1 = relu(relu(combine1) @ w1b + b1b) ; pool into pooled
    combine_gemm_pool_kernel<<<gemm_blocks, NTHREADS, SMEM_BYTES>>>(bufA, bufB, eps1, b1a, w1b, b1b, batch, pooled);
    // K7: logits + log_softmax
    head_kernel<<<2, 256>>>(pooled, fcw, fcb, out);
}

// round 13
// speedup vs baseline: 1.1861x; 1.1861x over previous
#include <cuda_runtime.h>
#include <cstdint>

#define N_NODES  50000
#define N_EDGES  800000
#define IN_CH    128
#define HID      64
#define N_GRAPHS 512
#define OUT_CH   10

#define TILE_ROWS 64
#define NTHREADS  128
#define SX_STRIDE 68                    // 16B-aligned, conflict-free for row-diff 1
#define SMEM_BYTES (TILE_ROWS * SX_STRIDE * 4 + 64 * 64 * 4)   // 33792

// ---------------- scratch (static device memory; no allocations) ------------
__device__ float g_bufA[N_NODES * HID];   // y (pre-agg features)
__device__ float g_bufB[N_NODES * HID];   // agg buffer (atomics target)
__device__ float g_bufC[N_NODES * HID];   // h0
__device__ float g_pooled[N_GRAPHS * HID];

// ---------------- packed f32x2 helpers --------------------------------------
#define FMA2(acc, a, b) \
    asm("fma.rn.f32x2 %0, %1, %2, %0;" : "+l"(acc) : "l"(a), "l"(b))
#define PACK2(out, x) \
    asm("mov.b64 %0, {%1, %1};" : "=l"(out) : "r"(__float_as_uint(x)))
#define UNPACK2(lo, hi, in) \
    asm("mov.b64 {%0, %1}, %2;" : "=r"(lo), "=r"(hi) : "l"(in))

// ============================================================================
// Shared GEMM core (64x64 tile, 128 threads, 8 rows x 4 cols per thread,
// accumulators as 8 x 2 packed f32x2 col-pairs -> fma.rn.f32x2)
// Thread t: cols [tc*4, tc*4+4), rows {tr + 8*i}, tc = t&15, tr = t>>4 (0..7).
// PROVEN R11 core: float4 (LDS.128) x-loads, PACK2 per 2 FMA2s.
// ============================================================================

#define GEMM_ACC_DECL  unsigned long long acc01[8] = {}, acc23[8] = {}

#define GEMM_COMPUTE_CHUNK(sX, sW)                                            \
    _Pragma("unroll 4")                                                       \
    for (int k = 0; k < 64; k += 4) {                                         \
        ulonglong2 wv0 = *(const ulonglong2*)&sW[(k + 0) * 64 + tc * 4];      \
        ulonglong2 wv1 = *(const ulonglong2*)&sW[(k + 1) * 64 + tc * 4];      \
        ulonglong2 wv2 = *(const ulonglong2*)&sW[(k + 2) * 64 + tc * 4];      \
        ulonglong2 wv3 = *(const ulonglong2*)&sW[(k + 3) * 64 + tc * 4];      \
        _Pragma("unroll")                                                     \
        for (int i = 0; i < 8; ++i) {                                         \
            float4 xv = *(const float4*)&sX[(tr + 8 * i) * SX_STRIDE + k];    \
            unsigned long long xx;                                            \
            PACK2(xx, xv.x);                                                  \
            FMA2(acc01[i], xx, wv0.x); FMA2(acc23[i], xx, wv0.y);             \
            PACK2(xx, xv.y);                                                  \
            FMA2(acc01[i], xx, wv1.x); FMA2(acc23[i], xx, wv1.y);             \
            PACK2(xx, xv.z);                                                  \
            FMA2(acc01[i], xx, wv2.x); FMA2(acc23[i], xx, wv2.y);             \
            PACK2(xx, xv.w);                                                  \
            FMA2(acc01[i], xx, wv3.x); FMA2(acc23[i], xx, wv3.y);             \
        }                                                                     \
    }

// unpack row i's 4 accumulated columns into float4 o
#define GEMM_UNPACK_ROW(i, o)                                                 \
    {                                                                         \
        unsigned int u0, u1, u2, u3;                                          \
        UNPACK2(u0, u1, acc01[i]);                                            \
        UNPACK2(u2, u3, acc23[i]);                                            \
        o.x = __uint_as_float(u0); o.y = __uint_as_float(u1);                 \
        o.z = __uint_as_float(u2); o.w = __uint_as_float(u3);                 \
    }

// load 64x64 W chunk (row-major, contiguous) into sW via float4
#define LOAD_W_CHUNK(sW, Wptr)                                                \
    _Pragma("unroll")                                                         \
    for (int i = 0; i < 8; ++i) {                                             \
        int f4 = tid + i * NTHREADS;       /* 1024 float4s */                 \
        *(float4*)&sW[f4 * 4] = *(const float4*)&(Wptr)[f4 * 4];              \
    }

// ============================================================================
// K1: y0 = x @ w0a  (K=128). Tail: zero agg rows; block 0 zeroes pooled.
// ============================================================================
__global__ void __launch_bounds__(NTHREADS) gemm_in_kernel(
    const float* __restrict__ A, const float* __restrict__ W,
    float* __restrict__ out, float* __restrict__ aggz, float* __restrict__ pooled)
{
    extern __shared__ float smem[];
    float* sX = smem;
    float* sW = smem + TILE_ROWS * SX_STRIDE;

    const int tid = threadIdx.x;
    const int tc = tid & 15;
    const int tr = tid >> 4;
    const int row0 = blockIdx.x * TILE_ROWS;

    GEMM_ACC_DECL;

    for (int kc = 0; kc < IN_CH; kc += 64) {
        LOAD_W_CHUNK(sW, W + kc * 64)
#pragma unroll
        for (int i = 0; i < 8; ++i) {
            int f4 = tid + i * NTHREADS;       // 1024 float4s = 64 rows x 16
            int r = f4 >> 4, c4 = f4 & 15;
            int row = row0 + r;
            float4 v = make_float4(0.f, 0.f, 0.f, 0.f);
            if (row < N_NODES)
                v = *(const float4*)&A[(size_t)row * IN_CH + kc + c4 * 4];
            *(float4*)&sX[r * SX_STRIDE + c4 * 4] = v;
        }
        __syncthreads();
        GEMM_COMPUTE_CHUNK(sX, sW)
        __syncthreads();
    }

#pragma unroll
    for (int i = 0; i < 8; ++i) {
        int row = row0 + tr + 8 * i;
        if (row < N_NODES) {
            float4 o;
            GEMM_UNPACK_ROW(i, o)
            *(float4*)&out[(size_t)row * 64 + tc * 4] = o;
        }
    }

    const float4 z4 = make_float4(0.f, 0.f, 0.f, 0.f);
#pragma unroll
    for (int i = 0; i < 8; ++i) {
        int f4 = tid + i * NTHREADS;
        int row = row0 + (f4 >> 4);
        if (row < N_NODES)
            *(float4*)&aggz[(size_t)row * 64 + (f4 & 15) * 4] = z4;
    }
    if (blockIdx.x == 0) {
        for (int i = tid; i < N_GRAPHS * HID / 4; i += NTHREADS)
            ((float4*)pooled)[i] = z4;
    }
}

// ============================================================================
// Edge aggregation (8 edges/thread, red.global.add.v4) — proven kernel.
// ============================================================================
#define E_PER 8
__global__ void __launch_bounds__(256) edge_agg_kernel(
    const float* __restrict__ y, const int* __restrict__ ei,
    float* __restrict__ agg)
{
    const int t = blockIdx.x * blockDim.x + threadIdx.x;
    const int c4 = t & 15;
    const int eb = (t >> 4) * E_PER;
    if (eb >= N_EDGES) return;

    int s[E_PER], d[E_PER];
#pragma unroll
    for (int j = 0; j < E_PER; ++j) {
        s[j] = __ldg(&ei[eb + j]);
        d[j] = __ldg(&ei[N_EDGES + eb + j]);
    }
    float4 v[E_PER];
#pragma unroll
    for (int j = 0; j < E_PER; ++j)
        v[j] = *(const float4*)(y + (size_t)s[j] * 64 + c4 * 4);
#pragma unroll
    for (int j = 0; j < E_PER; ++j) {
        float* p = agg + (size_t)d[j] * 64 + c4 * 4;
        asm volatile("red.global.add.v4.f32 [%0], {%1,%2,%3,%4};"
                     :: "l"(p), "f"(v[j].x), "f"(v[j].y), "f"(v[j].z), "f"(v[j].w)
                     : "memory");
    }
}

// ============================================================================
// K3: combine + GEMM:  out = relu( relu((1+eps)*A + G + preb) @ W + bias )
//     Also zeroes G behind the read (prepares bufB for layer-1 atomics).
// ============================================================================
__global__ void __launch_bounds__(NTHREADS) combine_gemm_kernel(
    const float* __restrict__ A, float* __restrict__ G,
    const float* __restrict__ epsp, const float* __restrict__ preb,
    const float* __restrict__ W, const float* __restrict__ bias,
    float* __restrict__ out)
{
    extern __shared__ float smem[];
    float* sX = smem;
    float* sW = smem + TILE_ROWS * SX_STRIDE;

    const int tid = threadIdx.x;
    const int tc = tid & 15;
    const int tr = tid >> 4;
    const int row0 = blockIdx.x * TILE_ROWS;
    const float epsf = 1.0f + __ldg(&epsp[0]);
    const float4 z4 = make_float4(0.f, 0.f, 0.f, 0.f);

    LOAD_W_CHUNK(sW, W)
#pragma unroll
    for (int i = 0; i < 8; ++i) {
        int f4 = tid + i * NTHREADS;
        int r = f4 >> 4, c4 = f4 & 15;
        int row = row0 + r;
        float4 v = make_float4(0.f, 0.f, 0.f, 0.f);
        if (row < N_NODES) {
            size_t off = (size_t)row * 64 + c4 * 4;
            float4 a = *(const float4*)&A[off];
            float4 g = *(const float4*)&G[off];
            float4 pb = *(const float4*)&preb[c4 * 4];
            v.x = fmaxf(fmaf(epsf, a.x, g.x) + pb.x, 0.f);
            v.y = fmaxf(fmaf(epsf, a.y, g.y) + pb.y, 0.f);
            v.z = fmaxf(fmaf(epsf, a.z, g.z) + pb.z, 0.f);
            v.w = fmaxf(fmaf(epsf, a.w, g.w) + pb.w, 0.f);
            *(float4*)&G[off] = z4;          // re-zero for layer-1 aggregation
        }
        *(float4*)&sX[r * SX_STRIDE + c4 * 4] = v;
    }
    __syncthreads();

    GEMM_ACC_DECL;
    GEMM_COMPUTE_CHUNK(sX, sW)

    const float4 bv = *(const float4*)&bias[tc * 4];
#pragma unroll
    for (int i = 0; i < 8; ++i) {
        int row = row0 + tr + 8 * i;
        if (row < N_NODES) {
            float4 o;
            GEMM_UNPACK_ROW(i, o)
            o.x = fmaxf(o.x + bv.x, 0.f);
            o.y = fmaxf(o.y + bv.y, 0.f);
            o.z = fmaxf(o.z + bv.z, 0.f);
            o.w = fmaxf(o.w + bv.w, 0.f);
            *(float4*)&out[(size_t)row * 64 + tc * 4] = o;
        }
    }
}

// ============================================================================
// K4: pure GEMM: out = A @ W   (no tail work)
// ============================================================================
__global__ void __launch_bounds__(NTHREADS) gemm64_kernel(
    const float* __restrict__ A, const float* __restrict__ W,
    float* __restrict__ out)
{
    extern __shared__ float smem[];
    float* sX = smem;
    float* sW = smem + TILE_ROWS * SX_STRIDE;

    const int tid = threadIdx.x;
    const int tc = tid & 15;
    const int tr = tid >> 4;
    const int row0 = blockIdx.x * TILE_ROWS;

    LOAD_W_CHUNK(sW, W)
#pragma unroll
    for (int i = 0; i < 8; ++i) {
        int f4 = tid + i * NTHREADS;
        int r = f4 >> 4, c4 = f4 & 15;
        int row = row0 + r;
        float4 v = make_float4(0.f, 0.f, 0.f, 0.f);
        if (row < N_NODES)
            v = *(const float4*)&A[(size_t)row * 64 + c4 * 4];
        *(float4*)&sX[r * SX_STRIDE + c4 * 4] = v;
    }
    __syncthreads();

    GEMM_ACC_DECL;
    GEMM_COMPUTE_CHUNK(sX, sW)

#pragma unroll
    for (int i = 0; i < 8; ++i) {
        int row = row0 + tr + 8 * i;
        if (row < N_NODES) {
            float4 o;
            GEMM_UNPACK_ROW(i, o)
            *(float4*)&out[(size_t)row * 64 + tc * 4] = o;
        }
    }
}

// ============================================================================
// K6: combine + GEMM + pool (h1 never hits global)
// ============================================================================
__global__ void __launch_bounds__(NTHREADS) combine_gemm_pool_kernel(
    const float* __restrict__ A, const float* __restrict__ G,
    const float* __restrict__ epsp, const float* __restrict__ preb,
    const float* __restrict__ W, const float* __restrict__ bias,
    const int* __restrict__ batch, float* __restrict__ pooled)
{
    extern __shared__ float smem[];
    float* sX = smem;
    float* sW = smem + TILE_ROWS * SX_STRIDE;

    const int tid = threadIdx.x;
    const int tc = tid & 15;
    const int tr = tid >> 4;
    const int row0 = blockIdx.x * TILE_ROWS;
    const float epsf = 1.0f + __ldg(&epsp[0]);

    LOAD_W_CHUNK(sW, W)
#pragma unroll
    for (int i = 0; i < 8; ++i) {
        int f4 = tid + i * NTHREADS;
        int r = f4 >> 4, c4 = f4 & 15;
        int row = row0 + r;
        float4 v = make_float4(0.f, 0.f, 0.f, 0.f);
        if (row < N_NODES) {
            size_t off = (size_t)row * 64 + c4 * 4;
            float4 a = *(const float4*)&A[off];
            float4 g = *(const float4*)&G[off];
            float4 pb = *(const float4*)&preb[c4 * 4];
            v.x = fmaxf(fmaf(epsf, a.x, g.x) + pb.x, 0.f);
            v.y = fmaxf(fmaf(epsf, a.y, g.y) + pb.y, 0.f);
            v.z = fmaxf(fmaf(epsf, a.z, g.z) + pb.z, 0.f);
            v.w = fmaxf(fmaf(epsf, a.w, g.w) + pb.w, 0.f);
        }
        *(float4*)&sX[r * SX_STRIDE + c4 * 4] = v;
    }
    __syncthreads();

    GEMM_ACC_DECL;
    GEMM_COMPUTE_CHUNK(sX, sW)

    const float4 bv = *(const float4*)&bias[tc * 4];
#pragma unroll
    for (int i = 0; i < 8; ++i) {
        int row = row0 + tr + 8 * i;
        if (row < N_NODES) {
            int g = __ldg(&batch[row]);
            float4 o;
            GEMM_UNPACK_ROW(i, o)
            o.x = fmaxf(o.x + bv.x, 0.f);
            o.y = fmaxf(o.y + bv.y, 0.f);
            o.z = fmaxf(o.z + bv.z, 0.f);
            o.w = fmaxf(o.w + bv.w, 0.f);
            float* p = pooled + (size_t)g * 64 + tc * 4;
            asm volatile("red.global.add.v4.f32 [%0], {%1,%2,%3,%4};"
                         :: "l"(p), "f"(o.x), "f"(o.y), "f"(o.z), "f"(o.w) : "memory");
        }
    }
}

// ============================================================================
// K7: head: logits + log_softmax
// ============================================================================
__global__ void __launch_bounds__(256) head_kernel(
    const float* __restrict__ pooled, const float* __restrict__ fcw,
    const float* __restrict__ fcb, float* __restrict__ out)
{
    int g = blockIdx.x * blockDim.x + threadIdx.x;
    if (g >= N_GRAPHS) return;
    float logit[OUT_CH];
#pragma unroll
    for (int j = 0; j < OUT_CH; ++j) logit[j] = __ldg(&fcb[j]);
#pragma unroll 8
    for (int k = 0; k < HID; ++k) {
        float p = pooled[g * HID + k];
#pragma unroll
        for (int j = 0; j < OUT_CH; ++j)
            logit[j] += p * __ldg(&fcw[k * OUT_CH + j]);
    }
    float m = logit[0];
#pragma unroll
    for (int j = 1; j < OUT_CH; ++j) m = fmaxf(m, logit[j]);
    float s = 0.f;
#pragma unroll
    for (int j = 0; j < OUT_CH; ++j) s += __expf(logit[j] - m);
    float ls = m + logf(s);
#pragma unroll
    for (int j = 0; j < OUT_CH; ++j) out[g * OUT_CH + j] = logit[j] - ls;
}

// ---------------- launch ----------------------------------------------------
extern "C" void kernel_launch(void* const* d_in, const int* in_sizes, int n_in,
                              void* d_out, int out_size)
{
    const float* x    = (const float*)d_in[0];
    const int*   ei   = (const int*)d_in[1];
    const int*   batch= (const int*)d_in[2];
    const float* eps0 = (const float*)d_in[3];
    const float* w0a  = (const float*)d_in[4];
    const float* b0a  = (const float*)d_in[5];
    const float* w0b  = (const float*)d_in[6];
    const float* b0b  = (const float*)d_in[7];
    const float* eps1 = (const float*)d_in[8];
    const float* w1a  = (const float*)d_in[9];
    const float* b1a  = (const float*)d_in[10];
    const float* w1b  = (const float*)d_in[11];
    const float* b1b  = (const float*)d_in[12];
    const float* fcw  = (const float*)d_in[13];
    const float* fcb  = (const float*)d_in[14];
    float*       out  = (float*)d_out;

    float *bufA, *bufB, *bufC, *pooled;
    cudaGetSymbolAddress((void**)&bufA, g_bufA);
    cudaGetSymbolAddress((void**)&bufB, g_bufB);
    cudaGetSymbolAddress((void**)&bufC, g_bufC);
    cudaGetSymbolAddress((void**)&pooled, g_pooled);

    static bool attr_done = false;
    if (!attr_done) {
        cudaFuncSetAttribute(gemm_in_kernel,
            cudaFuncAttributeMaxDynamicSharedMemorySize, SMEM_BYTES);
        cudaFuncSetAttribute(combine_gemm_kernel,
            cudaFuncAttributeMaxDynamicSharedMemorySize, SMEM_BYTES);
        cudaFuncSetAttribute(gemm64_kernel,
            cudaFuncAttributeMaxDynamicSharedMemorySize, SMEM_BYTES);
        cudaFuncSetAttribute(combine_gemm_pool_kernel,
            cudaFuncAttributeMaxDynamicSharedMemorySize, SMEM_BYTES);
        attr_done = true;
    }

    const int gemm_blocks = (N_NODES + TILE_ROWS - 1) / TILE_ROWS;   // 782
    const int edge_blocks = (N_EDGES / E_PER * 16 + 255) / 256;      // 6250

    // K1: y0 = x @ w0a ; zero bufB + pooled
    gemm_in_kernel<<<gemm_blocks, NTHREADS, SMEM_BYTES>>>(x, w0a, bufA, bufB, pooled);
    // K2: agg0 = scatter-add(y0)
    edge_agg_kernel<<<edge_blocks, 256>>>(bufA, ei, bufB);
    // K3: h0 = relu(relu(combine0) @ w0b + b0b) ; re-zero bufB behind the read
    combine_gemm_kernel<<<gemm_blocks, NTHREADS, SMEM_BYTES>>>(bufA, bufB, eps0, b0a, w0b, b0b, bufC);
    // K4: y1 = h0 @ w1a  (pure GEMM)
    gemm64_kernel<<<gemm_blocks, NTHREADS, SMEM_BYTES>>>(bufC, w1a, bufA);
    // K5: agg1 = scatter-add(y1)
    edge_agg_kernel<<<edge_blocks, 256>>>(bufA, ei, bufB);
    // K6: h1 = relu(relu(combine1) @ w1b + b1b) ; pool into pooled
    combine_gemm_pool_kernel<<<gemm_blocks, NTHREADS, SMEM_BYTES>>>(bufA, bufB, eps1, b1a, w1b, b1b, batch, pooled);
    // K7: logits + log_softmax
    head_kernel<<<2, 256>>>(pooled, fcw, fcb, out);
}

// round 14
// speedup vs baseline: 1.3716x; 1.1563x over previous
#include <cuda_runtime.h>
#include <cstdint>

#define N_NODES  50000
#define N_EDGES  800000
#define IN_CH    128
#define HID      64
#define N_GRAPHS 512
#define OUT_CH   10

#define TILE_ROWS 64
#define NTHREADS  128
#define SX_STRIDE 68                    // 16B-aligned, conflict-free for row-diff 1
#define SMEM_BYTES (TILE_ROWS * SX_STRIDE * 4 + 64 * 64 * 4)   // 33792

// ---------------- scratch (static device memory; no allocations) ------------
__device__ float g_bufA[N_NODES * HID];   // y (pre-agg features)
__device__ float g_bufB[N_NODES * HID];   // agg buffer (atomics target)
__device__ float g_bufC[N_NODES * HID];   // h0
__device__ float g_pooled[N_GRAPHS * HID];

// ---------------- packed f32x2 helpers --------------------------------------
#define FMA2(acc, a, b) \
    asm("fma.rn.f32x2 %0, %1, %2, %0;" : "+l"(acc) : "l"(a), "l"(b))
#define PACK2(out, x) \
    asm("mov.b64 %0, {%1, %1};" : "=l"(out) : "r"(__float_as_uint(x)))
#define UNPACK2(lo, hi, in) \
    asm("mov.b64 {%0, %1}, %2;" : "=r"(lo), "=r"(hi) : "l"(in))

// ============================================================================
// Shared GEMM core (64x64 tile, 128 threads, 8 rows x 4 cols per thread,
// accumulators as 8 x 2 packed f32x2 col-pairs -> fma.rn.f32x2)
// Thread t: cols [tc*4, tc*4+4), rows {tr + 8*i}, tc = t&15, tr = t>>4 (0..7).
// ============================================================================

#define GEMM_ACC_DECL  unsigned long long acc01[8] = {}, acc23[8] = {}

#define GEMM_COMPUTE_CHUNK(sX, sW)                                            \
    _Pragma("unroll 4")                                                       \
    for (int k = 0; k < 64; k += 4) {                                         \
        ulonglong2 wv0 = *(const ulonglong2*)&sW[(k + 0) * 64 + tc * 4];      \
        ulonglong2 wv1 = *(const ulonglong2*)&sW[(k + 1) * 64 + tc * 4];      \
        ulonglong2 wv2 = *(const ulonglong2*)&sW[(k + 2) * 64 + tc * 4];      \
        ulonglong2 wv3 = *(const ulonglong2*)&sW[(k + 3) * 64 + tc * 4];      \
        _Pragma("unroll")                                                     \
        for (int i = 0; i < 8; ++i) {                                         \
            float4 xv = *(const float4*)&sX[(tr + 8 * i) * SX_STRIDE + k];    \
            unsigned long long xx;                                            \
            PACK2(xx, xv.x);                                                  \
            FMA2(acc01[i], xx, wv0.x); FMA2(acc23[i], xx, wv0.y);             \
            PACK2(xx, xv.y);                                                  \
            FMA2(acc01[i], xx, wv1.x); FMA2(acc23[i], xx, wv1.y);             \
            PACK2(xx, xv.z);                                                  \
            FMA2(acc01[i], xx, wv2.x); FMA2(acc23[i], xx, wv2.y);             \
            PACK2(xx, xv.w);                                                  \
            FMA2(acc01[i], xx, wv3.x); FMA2(acc23[i], xx, wv3.y);             \
        }                                                                     \
    }

// unpack row i's 4 accumulated columns into float4 o
#define GEMM_UNPACK_ROW(i, o)                                                 \
    {                                                                         \
        unsigned int u0, u1, u2, u3;                                          \
        UNPACK2(u0, u1, acc01[i]);                                            \
        UNPACK2(u2, u3, acc23[i]);                                            \
        o.x = __uint_as_float(u0); o.y = __uint_as_float(u1);                 \
        o.z = __uint_as_float(u2); o.w = __uint_as_float(u3);                 \
    }

// load 64x64 W chunk (row-major, contiguous) into sW via float4
#define LOAD_W_CHUNK(sW, Wptr)                                                \
    _Pragma("unroll")                                                         \
    for (int i = 0; i < 8; ++i) {                                             \
        int f4 = tid + i * NTHREADS;       /* 1024 float4s */                 \
        *(float4*)&sW[f4 * 4] = *(const float4*)&(Wptr)[f4 * 4];              \
    }

// ============================================================================
// K1: y0 = x @ w0a  (K=128). Tail: zero agg rows; block 0 zeroes pooled.
// ============================================================================
__global__ void __launch_bounds__(NTHREADS) gemm_in_kernel(
    const float* __restrict__ A, const float* __restrict__ W,
    float* __restrict__ out, float* __restrict__ aggz, float* __restrict__ pooled)
{
    extern __shared__ float smem[];
    float* sX = smem;
    float* sW = smem + TILE_ROWS * SX_STRIDE;

    const int tid = threadIdx.x;
    const int tc = tid & 15;
    const int tr = tid >> 4;
    const int row0 = blockIdx.x * TILE_ROWS;

    GEMM_ACC_DECL;

    for (int kc = 0; kc < IN_CH; kc += 64) {
        LOAD_W_CHUNK(sW, W + kc * 64)
#pragma unroll
        for (int i = 0; i < 8; ++i) {
            int f4 = tid + i * NTHREADS;       // 1024 float4s = 64 rows x 16
            int r = f4 >> 4, c4 = f4 & 15;
            int row = row0 + r;
            float4 v = make_float4(0.f, 0.f, 0.f, 0.f);
            if (row < N_NODES)
                v = *(const float4*)&A[(size_t)row * IN_CH + kc + c4 * 4];
            *(float4*)&sX[r * SX_STRIDE + c4 * 4] = v;
        }
        __syncthreads();
        GEMM_COMPUTE_CHUNK(sX, sW)
        __syncthreads();
    }

#pragma unroll
    for (int i = 0; i < 8; ++i) {
        int row = row0 + tr + 8 * i;
        if (row < N_NODES) {
            float4 o;
            GEMM_UNPACK_ROW(i, o)
            *(float4*)&out[(size_t)row * 64 + tc * 4] = o;
        }
    }

    const float4 z4 = make_float4(0.f, 0.f, 0.f, 0.f);
#pragma unroll
    for (int i = 0; i < 8; ++i) {
        int f4 = tid + i * NTHREADS;
        int row = row0 + (f4 >> 4);
        if (row < N_NODES)
            *(float4*)&aggz[(size_t)row * 64 + (f4 & 15) * 4] = z4;
    }
    if (blockIdx.x == 0) {
        for (int i = tid; i < N_GRAPHS * HID / 4; i += NTHREADS)
            ((float4*)pooled)[i] = z4;
    }
}

// ============================================================================
// Edge aggregation (8 edges/thread, red.global.add.v4) — proven kernel.
// ============================================================================
#define E_PER 8
__global__ void __launch_bounds__(256) edge_agg_kernel(
    const float* __restrict__ y, const int* __restrict__ ei,
    float* __restrict__ agg)
{
    const int t = blockIdx.x * blockDim.x + threadIdx.x;
    const int c4 = t & 15;
    const int eb = (t >> 4) * E_PER;
    if (eb >= N_EDGES) return;

    int s[E_PER], d[E_PER];
#pragma unroll
    for (int j = 0; j < E_PER; ++j) {
        s[j] = __ldg(&ei[eb + j]);
        d[j] = __ldg(&ei[N_EDGES + eb + j]);
    }
    float4 v[E_PER];
#pragma unroll
    for (int j = 0; j < E_PER; ++j)
        v[j] = *(const float4*)(y + (size_t)s[j] * 64 + c4 * 4);
#pragma unroll
    for (int j = 0; j < E_PER; ++j) {
        float* p = agg + (size_t)d[j] * 64 + c4 * 4;
        asm volatile("red.global.add.v4.f32 [%0], {%1,%2,%3,%4};"
                     :: "l"(p), "f"(v[j].x), "f"(v[j].y), "f"(v[j].z), "f"(v[j].w)
                     : "memory");
    }
}

// ============================================================================
// K3: combine + GEMM:  out = relu( relu((1+eps)*A + G + preb) @ W + bias )
// ============================================================================
__global__ void __launch_bounds__(NTHREADS) combine_gemm_kernel(
    const float* __restrict__ A, const float* __restrict__ G,
    const float* __restrict__ epsp, const float* __restrict__ preb,
    const float* __restrict__ W, const float* __restrict__ bias,
    float* __restrict__ out)
{
    extern __shared__ float smem[];
    float* sX = smem;
    float* sW = smem + TILE_ROWS * SX_STRIDE;

    const int tid = threadIdx.x;
    const int tc = tid & 15;
    const int tr = tid >> 4;
    const int row0 = blockIdx.x * TILE_ROWS;
    const float epsf = 1.0f + __ldg(&epsp[0]);

    LOAD_W_CHUNK(sW, W)
#pragma unroll
    for (int i = 0; i < 8; ++i) {
        int f4 = tid + i * NTHREADS;
        int r = f4 >> 4, c4 = f4 & 15;
        int row = row0 + r;
        float4 v = make_float4(0.f, 0.f, 0.f, 0.f);
        if (row < N_NODES) {
            size_t off = (size_t)row * 64 + c4 * 4;
            float4 a = *(const float4*)&A[off];
            float4 g = *(const float4*)&G[off];
            float4 pb = *(const float4*)&preb[c4 * 4];
            v.x = fmaxf(fmaf(epsf, a.x, g.x) + pb.x, 0.f);
            v.y = fmaxf(fmaf(epsf, a.y, g.y) + pb.y, 0.f);
            v.z = fmaxf(fmaf(epsf, a.z, g.z) + pb.z, 0.f);
            v.w = fmaxf(fmaf(epsf, a.w, g.w) + pb.w, 0.f);
        }
        *(float4*)&sX[r * SX_STRIDE + c4 * 4] = v;
    }
    __syncthreads();

    GEMM_ACC_DECL;
    GEMM_COMPUTE_CHUNK(sX, sW)

    const float4 bv = *(const float4*)&bias[tc * 4];
#pragma unroll
    for (int i = 0; i < 8; ++i) {
        int row = row0 + tr + 8 * i;
        if (row < N_NODES) {
            float4 o;
            GEMM_UNPACK_ROW(i, o)
            o.x = fmaxf(o.x + bv.x, 0.f);
            o.y = fmaxf(o.y + bv.y, 0.f);
            o.z = fmaxf(o.z + bv.z, 0.f);
            o.w = fmaxf(o.w + bv.w, 0.f);
            *(float4*)&out[(size_t)row * 64 + tc * 4] = o;
        }
    }
}

// ============================================================================
// K4: plain GEMM: out = A @ W ; tail: re-zero agg buffer rows
// ============================================================================
__global__ void __launch_bounds__(NTHREADS) gemm64_zero_kernel(
    const float* __restrict__ A, const float* __restrict__ W,
    float* __restrict__ out, float* __restrict__ aggz)
{
    extern __shared__ float smem[];
    float* sX = smem;
    float* sW = smem + TILE_ROWS * SX_STRIDE;

    const int tid = threadIdx.x;
    const int tc = tid & 15;
    const int tr = tid >> 4;
    const int row0 = blockIdx.x * TILE_ROWS;

    LOAD_W_CHUNK(sW, W)
#pragma unroll
    for (int i = 0; i < 8; ++i) {
        int f4 = tid + i * NTHREADS;
        int r = f4 >> 4, c4 = f4 & 15;
        int row = row0 + r;
        float4 v = make_float4(0.f, 0.f, 0.f, 0.f);
        if (row < N_NODES)
            v = *(const float4*)&A[(size_t)row * 64 + c4 * 4];
        *(float4*)&sX[r * SX_STRIDE + c4 * 4] = v;
    }
    __syncthreads();

    GEMM_ACC_DECL;
    GEMM_COMPUTE_CHUNK(sX, sW)

#pragma unroll
    for (int i = 0; i < 8; ++i) {
        int row = row0 + tr + 8 * i;
        if (row < N_NODES) {
            float4 o;
            GEMM_UNPACK_ROW(i, o)
            *(float4*)&out[(size_t)row * 64 + tc * 4] = o;
        }
    }

    const float4 z4 = make_float4(0.f, 0.f, 0.f, 0.f);
#pragma unroll
    for (int i = 0; i < 8; ++i) {
        int f4 = tid + i * NTHREADS;
        int row = row0 + (f4 >> 4);
        if (row < N_NODES)
            *(float4*)&aggz[(size_t)row * 64 + (f4 & 15) * 4] = z4;
    }
}

// ============================================================================
// K6: combine + GEMM + pool (h1 never hits global)
// ============================================================================
__global__ void __launch_bounds__(NTHREADS) combine_gemm_pool_kernel(
    const float* __restrict__ A, const float* __restrict__ G,
    const float* __restrict__ epsp, const float* __restrict__ preb,
    const float* __restrict__ W, const float* __restrict__ bias,
    const int* __restrict__ batch, float* __restrict__ pooled)
{
    extern __shared__ float smem[];
    float* sX = smem;
    float* sW = smem + TILE_ROWS * SX_STRIDE;

    const int tid = threadIdx.x;
    const int tc = tid & 15;
    const int tr = tid >> 4;
    const int row0 = blockIdx.x * TILE_ROWS;
    const float epsf = 1.0f + __ldg(&epsp[0]);

    LOAD_W_CHUNK(sW, W)
#pragma unroll
    for (int i = 0; i < 8; ++i) {
        int f4 = tid + i * NTHREADS;
        int r = f4 >> 4, c4 = f4 & 15;
        int row = row0 + r;
        float4 v = make_float4(0.f, 0.f, 0.f, 0.f);
        if (row < N_NODES) {
            size_t off = (size_t)row * 64 + c4 * 4;
            float4 a = *(const float4*)&A[off];
            float4 g = *(const float4*)&G[off];
            float4 pb = *(const float4*)&preb[c4 * 4];
            v.x = fmaxf(fmaf(epsf, a.x, g.x) + pb.x, 0.f);
            v.y = fmaxf(fmaf(epsf, a.y, g.y) + pb.y, 0.f);
            v.z = fmaxf(fmaf(epsf, a.z, g.z) + pb.z, 0.f);
            v.w = fmaxf(fmaf(epsf, a.w, g.w) + pb.w, 0.f);
        }
        *(float4*)&sX[r * SX_STRIDE + c4 * 4] = v;
    }
    __syncthreads();

    GEMM_ACC_DECL;
    GEMM_COMPUTE_CHUNK(sX, sW)

    const float4 bv = *(const float4*)&bias[tc * 4];
#pragma unroll
    for (int i = 0; i < 8; ++i) {
        int row = row0 + tr + 8 * i;
        if (row < N_NODES) {
            int g = __ldg(&batch[row]);
            float4 o;
            GEMM_UNPACK_ROW(i, o)
            o.x = fmaxf(o.x + bv.x, 0.f);
            o.y = fmaxf(o.y + bv.y, 0.f);
            o.z = fmaxf(o.z + bv.z, 0.f);
            o.w = fmaxf(o.w + bv.w, 0.f);
            float* p = pooled + (size_t)g * 64 + tc * 4;
            asm volatile("red.global.add.v4.f32 [%0], {%1,%2,%3,%4};"
                         :: "l"(p), "f"(o.x), "f"(o.y), "f"(o.z), "f"(o.w) : "memory");
        }
    }
}

// ============================================================================
// K7: head: logits + log_softmax
// ============================================================================
__global__ void __launch_bounds__(256) head_kernel(
    const float* __restrict__ pooled, const float* __restrict__ fcw,
    const float* __restrict__ fcb, float* __restrict__ out)
{
    int g = blockIdx.x * blockDim.x + threadIdx.x;
    if (g >= N_GRAPHS) return;
    float logit[OUT_CH];
#pragma unroll
    for (int j = 0; j < OUT_CH; ++j) logit[j] = __ldg(&fcb[j]);
#pragma unroll 8
    for (int k = 0; k < HID; ++k) {
        float p = pooled[g * HID + k];
#pragma unroll
        for (int j = 0; j < OUT_CH; ++j)
            logit[j] += p * __ldg(&fcw[k * OUT_CH + j]);
    }
    float m = logit[0];
#pragma unroll
    for (int j = 1; j < OUT_CH; ++j) m = fmaxf(m, logit[j]);
    float s = 0.f;
#pragma unroll
    for (int j = 0; j < OUT_CH; ++j) s += __expf(logit[j] - m);
    float ls = m + logf(s);
#pragma unroll
    for (int j = 0; j < OUT_CH; ++j) out[g * OUT_CH + j] = logit[j] - ls;
}

// ---------------- launch ----------------------------------------------------
extern "C" void kernel_launch(void* const* d_in, const int* in_sizes, int n_in,
                              void* d_out, int out_size)
{
    const float* x    = (const float*)d_in[0];
    const int*   ei   = (const int*)d_in[1];
    const int*   batch= (const int*)d_in[2];
    const float* eps0 = (const float*)d_in[3];
    const float* w0a  = (const float*)d_in[4];
    const float* b0a  = (const float*)d_in[5];
    const float* w0b  = (const float*)d_in[6];
    const float* b0b  = (const float*)d_in[7];
    const float* eps1 = (const float*)d_in[8];
    const float* w1a  = (const float*)d_in[9];
    const float* b1a  = (const float*)d_in[10];
    const float* w1b  = (const float*)d_in[11];
    const float* b1b  = (const float*)d_in[12];
    const float* fcw  = (const float*)d_in[13];
    const float* fcb  = (const float*)d_in[14];
    float*       out  = (float*)d_out;

    float *bufA, *bufB, *bufC, *pooled;
    cudaGetSymbolAddress((void**)&bufA, g_bufA);
    cudaGetSymbolAddress((void**)&bufB, g_bufB);
    cudaGetSymbolAddress((void**)&bufC, g_bufC);
    cudaGetSymbolAddress((void**)&pooled, g_pooled);

    static bool attr_done = false;
    if (!attr_done) {
        cudaFuncSetAttribute(gemm_in_kernel,
            cudaFuncAttributeMaxDynamicSharedMemorySize, SMEM_BYTES);
        cudaFuncSetAttribute(combine_gemm_kernel,
            cudaFuncAttributeMaxDynamicSharedMemorySize, SMEM_BYTES);
        cudaFuncSetAttribute(gemm64_zero_kernel,
            cudaFuncAttributeMaxDynamicSharedMemorySize, SMEM_BYTES);
        cudaFuncSetAttribute(combine_gemm_pool_kernel,
            cudaFuncAttributeMaxDynamicSharedMemorySize, SMEM_BYTES);
        attr_done = true;
    }

    const int gemm_blocks = (N_NODES + TILE_ROWS - 1) / TILE_ROWS;   // 782
    const int edge_blocks = (N_EDGES / E_PER * 16 + 255) / 256;      // 6250

    // K1: y0 = x @ w0a ; zero bufB + pooled
    gemm_in_kernel<<<gemm_blocks, NTHREADS, SMEM_BYTES>>>(x, w0a, bufA, bufB, pooled);
    // K2: agg0 = scatter-add(y0)
    edge_agg_kernel<<<edge_blocks, 256>>>(bufA, ei, bufB);
    // K3: h0 = relu(relu(combine0) @ w0b + b0b)
    combine_gemm_kernel<<<gemm_blocks, NTHREADS, SMEM_BYTES>>>(bufA, bufB, eps0, b0a, w0b, b0b, bufC);
    // K4: y1 = h0 @ w1a ; re-zero bufB
    gemm64_zero_kernel<<<gemm_blocks, NTHREADS, SMEM_BYTES>>>(bufC, w1a, bufA, bufB);
    // K5: agg1 = scatter-add(y1)
    edge_agg_kernel<<<edge_blocks, 256>>>(bufA, ei, bufB);
    // K6: h1 = relu(relu(combine1) @ w1b + b1b) ; pool into pooled
    combine_gemm_pool_kernel<<<gemm_blocks, NTHREADS, SMEM_BYTES>>>(bufA, bufB, eps1, b1a, w1b, b1b, batch, pooled);
    // K7: logits + log_softmax
    head_kernel<<<2, 256>>>(pooled, fcw, fcb, out);
}

// round 15
// speedup vs baseline: 1.3923x; 1.0152x over previous
#include <cuda_runtime.h>
#include <cstdint>

#define N_NODES  50000
#define N_EDGES  800000
#define IN_CH    128
#define HID      64
#define N_GRAPHS 512
#define OUT_CH   10

#define TILE_ROWS 64
#define NTHREADS  128
#define SX_STRIDE 68                    // 16B-aligned, conflict-free for row-diff 1
#define SMEM_BYTES (TILE_ROWS * SX_STRIDE * 4 + 64 * 64 * 4)   // 33792

// ---------------- scratch (static device memory; no allocations) ------------
__device__ float g_bufA[N_NODES * HID];   // y0
__device__ float g_bufB[N_NODES * HID];   // agg buffer (atomics target)
__device__ float g_bufC[N_NODES * HID];   // y1
__device__ float g_pooled[N_GRAPHS * HID];

// ---------------- packed f32x2 helpers --------------------------------------
#define FMA2(acc, a, b) \
    asm("fma.rn.f32x2 %0, %1, %2, %0;" : "+l"(acc) : "l"(a), "l"(b))
#define PACK2(out, x) \
    asm("mov.b64 %0, {%1, %1};" : "=l"(out) : "r"(__float_as_uint(x)))
#define UNPACK2(lo, hi, in) \
    asm("mov.b64 {%0, %1}, %2;" : "=r"(lo), "=r"(hi) : "l"(in))

// ============================================================================
// Shared GEMM core (64x64 tile, 128 threads, 8 rows x 4 cols per thread,
// accumulators as 8 x 2 packed f32x2 col-pairs -> fma.rn.f32x2)
// Thread t: cols [tc*4, tc*4+4), rows {tr + 8*i}, tc = t&15, tr = t>>4 (0..7).
// ============================================================================

#define GEMM_ACC_DECL  unsigned long long acc01[8] = {}, acc23[8] = {}
#define GEMM_ACC_ZERO                                                         \
    _Pragma("unroll")                                                         \
    for (int i = 0; i < 8; ++i) { acc01[i] = 0ull; acc23[i] = 0ull; }

#define GEMM_COMPUTE_CHUNK(sX, sW)                                            \
    _Pragma("unroll 4")                                                       \
    for (int k = 0; k < 64; k += 4) {                                         \
        ulonglong2 wv0 = *(const ulonglong2*)&sW[(k + 0) * 64 + tc * 4];      \
        ulonglong2 wv1 = *(const ulonglong2*)&sW[(k + 1) * 64 + tc * 4];      \
        ulonglong2 wv2 = *(const ulonglong2*)&sW[(k + 2) * 64 + tc * 4];      \
        ulonglong2 wv3 = *(const ulonglong2*)&sW[(k + 3) * 64 + tc * 4];      \
        _Pragma("unroll")                                                     \
        for (int i = 0; i < 8; ++i) {                                         \
            float4 xv = *(const float4*)&sX[(tr + 8 * i) * SX_STRIDE + k];    \
            unsigned long long xx;                                            \
            PACK2(xx, xv.x);                                                  \
            FMA2(acc01[i], xx, wv0.x); FMA2(acc23[i], xx, wv0.y);             \
            PACK2(xx, xv.y);                                                  \
            FMA2(acc01[i], xx, wv1.x); FMA2(acc23[i], xx, wv1.y);             \
            PACK2(xx, xv.z);                                                  \
            FMA2(acc01[i], xx, wv2.x); FMA2(acc23[i], xx, wv2.y);             \
            PACK2(xx, xv.w);                                                  \
            FMA2(acc01[i], xx, wv3.x); FMA2(acc23[i], xx, wv3.y);             \
        }                                                                     \
    }

// unpack row i's 4 accumulated columns into float4 o
#define GEMM_UNPACK_ROW(i, o)                                                 \
    {                                                                         \
        unsigned int u0, u1, u2, u3;                                          \
        UNPACK2(u0, u1, acc01[i]);                                            \
        UNPACK2(u2, u3, acc23[i]);                                            \
        o.x = __uint_as_float(u0); o.y = __uint_as_float(u1);                 \
        o.z = __uint_as_float(u2); o.w = __uint_as_float(u3);                 \
    }

// load 64x64 W chunk (row-major, contiguous) into sW via float4
#define LOAD_W_CHUNK(sW, Wptr)                                                \
    _Pragma("unroll")                                                         \
    for (int i = 0; i < 8; ++i) {                                             \
        int f4 = tid + i * NTHREADS;       /* 1024 float4s */                 \
        *(float4*)&sW[f4 * 4] = *(const float4*)&(Wptr)[f4 * 4];              \
    }

// ============================================================================
// K1: y0 = x @ w0a  (K=128). Tail: zero agg rows; block 0 zeroes pooled.
// ============================================================================
__global__ void __launch_bounds__(NTHREADS) gemm_in_kernel(
    const float* __restrict__ A, const float* __restrict__ W,
    float* __restrict__ out, float* __restrict__ aggz, float* __restrict__ pooled)
{
    extern __shared__ float smem[];
    float* sX = smem;
    float* sW = smem + TILE_ROWS * SX_STRIDE;

    const int tid = threadIdx.x;
    const int tc = tid & 15;
    const int tr = tid >> 4;
    const int row0 = blockIdx.x * TILE_ROWS;

    GEMM_ACC_DECL;

    for (int kc = 0; kc < IN_CH; kc += 64) {
        LOAD_W_CHUNK(sW, W + kc * 64)
#pragma unroll
        for (int i = 0; i < 8; ++i) {
            int f4 = tid + i * NTHREADS;       // 1024 float4s = 64 rows x 16
            int r = f4 >> 4, c4 = f4 & 15;
            int row = row0 + r;
            float4 v = make_float4(0.f, 0.f, 0.f, 0.f);
            if (row < N_NODES)
                v = *(const float4*)&A[(size_t)row * IN_CH + kc + c4 * 4];
            *(float4*)&sX[r * SX_STRIDE + c4 * 4] = v;
        }
        __syncthreads();
        GEMM_COMPUTE_CHUNK(sX, sW)
        __syncthreads();
    }

#pragma unroll
    for (int i = 0; i < 8; ++i) {
        int row = row0 + tr + 8 * i;
        if (row < N_NODES) {
            float4 o;
            GEMM_UNPACK_ROW(i, o)
            *(float4*)&out[(size_t)row * 64 + tc * 4] = o;
        }
    }

    const float4 z4 = make_float4(0.f, 0.f, 0.f, 0.f);
#pragma unroll
    for (int i = 0; i < 8; ++i) {
        int f4 = tid + i * NTHREADS;
        int row = row0 + (f4 >> 4);
        if (row < N_NODES)
            *(float4*)&aggz[(size_t)row * 64 + (f4 & 15) * 4] = z4;
    }
    if (blockIdx.x == 0) {
        for (int i = tid; i < N_GRAPHS * HID / 4; i += NTHREADS)
            ((float4*)pooled)[i] = z4;
    }
}

// ============================================================================
// Edge aggregation (8 edges/thread, red.global.add.v4) — proven kernel.
// ============================================================================
#define E_PER 8
__global__ void __launch_bounds__(256) edge_agg_kernel(
    const float* __restrict__ y, const int* __restrict__ ei,
    float* __restrict__ agg)
{
    const int t = blockIdx.x * blockDim.x + threadIdx.x;
    const int c4 = t & 15;
    const int eb = (t >> 4) * E_PER;
    if (eb >= N_EDGES) return;

    int s[E_PER], d[E_PER];
#pragma unroll
    for (int j = 0; j < E_PER; ++j) {
        s[j] = __ldg(&ei[eb + j]);
        d[j] = __ldg(&ei[N_EDGES + eb + j]);
    }
    float4 v[E_PER];
#pragma unroll
    for (int j = 0; j < E_PER; ++j)
        v[j] = *(const float4*)(y + (size_t)s[j] * 64 + c4 * 4);
#pragma unroll
    for (int j = 0; j < E_PER; ++j) {
        float* p = agg + (size_t)d[j] * 64 + c4 * 4;
        asm volatile("red.global.add.v4.f32 [%0], {%1,%2,%3,%4};"
                     :: "l"(p), "f"(v[j].x), "f"(v[j].y), "f"(v[j].z), "f"(v[j].w)
                     : "memory");
    }
}

// ============================================================================
// K3 (fused): T = relu( relu((1+eps)*A + G + preb) @ Wb + bb )   [smem only]
//             y1 = T @ Wn  -> out
// Tail: re-zero agg buffer rows (post-epilogue, proven-safe location).
// ============================================================================
__global__ void __launch_bounds__(NTHREADS) mlp_fuse_kernel(
    const float* __restrict__ A, const float* __restrict__ G,
    const float* __restrict__ epsp, const float* __restrict__ preb,
    const float* __restrict__ Wb, const float* __restrict__ bb,
    const float* __restrict__ Wn, float* __restrict__ out,
    float* __restrict__ aggz)
{
    extern __shared__ float smem[];
    float* sX = smem;
    float* sW = smem + TILE_ROWS * SX_STRIDE;

    const int tid = threadIdx.x;
    const int tc = tid & 15;
    const int tr = tid >> 4;
    const int row0 = blockIdx.x * TILE_ROWS;
    const float epsf = 1.0f + __ldg(&epsp[0]);

    // ---- stage combine into sX, Wb into sW ----
    LOAD_W_CHUNK(sW, Wb)
#pragma unroll
    for (int i = 0; i < 8; ++i) {
        int f4 = tid + i * NTHREADS;
        int r = f4 >> 4, c4 = f4 & 15;
        int row = row0 + r;
        float4 v = make_float4(0.f, 0.f, 0.f, 0.f);
        if (row < N_NODES) {
            size_t off = (size_t)row * 64 + c4 * 4;
            float4 a = *(const float4*)&A[off];
            float4 g = *(const float4*)&G[off];
            float4 pb = *(const float4*)&preb[c4 * 4];
            v.x = fmaxf(fmaf(epsf, a.x, g.x) + pb.x, 0.f);
            v.y = fmaxf(fmaf(epsf, a.y, g.y) + pb.y, 0.f);
            v.z = fmaxf(fmaf(epsf, a.z, g.z) + pb.z, 0.f);
            v.w = fmaxf(fmaf(epsf, a.w, g.w) + pb.w, 0.f);
        }
        *(float4*)&sX[r * SX_STRIDE + c4 * 4] = v;
    }
    __syncthreads();

    // ---- GEMM1: acc = Z @ Wb ----
    GEMM_ACC_DECL;
    GEMM_COMPUTE_CHUNK(sX, sW)
    __syncthreads();                       // all reads of sX/sW done

    // ---- T = relu(acc + bb) -> sX ; Wn -> sW ----
    {
        const float4 bv = *(const float4*)&bb[tc * 4];
#pragma unroll
        for (int i = 0; i < 8; ++i) {
            float4 o;
            GEMM_UNPACK_ROW(i, o)
            o.x = fmaxf(o.x + bv.x, 0.f);
            o.y = fmaxf(o.y + bv.y, 0.f);
            o.z = fmaxf(o.z + bv.z, 0.f);
            o.w = fmaxf(o.w + bv.w, 0.f);
            *(float4*)&sX[(tr + 8 * i) * SX_STRIDE + tc * 4] = o;
        }
    }
    LOAD_W_CHUNK(sW, Wn)
    __syncthreads();

    // ---- GEMM2: y1 = T @ Wn ----
    GEMM_ACC_ZERO
    GEMM_COMPUTE_CHUNK(sX, sW)

#pragma unroll
    for (int i = 0; i < 8; ++i) {
        int row = row0 + tr + 8 * i;
        if (row < N_NODES) {
            float4 o;
            GEMM_UNPACK_ROW(i, o)
            *(float4*)&out[(size_t)row * 64 + tc * 4] = o;
        }
    }

    // tail: re-zero agg buffer rows for layer-1 atomics
    const float4 z4 = make_float4(0.f, 0.f, 0.f, 0.f);
#pragma unroll
    for (int i = 0; i < 8; ++i) {
        int f4 = tid + i * NTHREADS;
        int row = row0 + (f4 >> 4);
        if (row < N_NODES)
            *(float4*)&aggz[(size_t)row * 64 + (f4 & 15) * 4] = z4;
    }
}

// ============================================================================
// K6: combine + GEMM + pool (h1 never hits global)
// ============================================================================
__global__ void __launch_bounds__(NTHREADS) combine_gemm_pool_kernel(
    const float* __restrict__ A, const float* __restrict__ G,
    const float* __restrict__ epsp, const float* __restrict__ preb,
    const float* __restrict__ W, const float* __restrict__ bias,
    const int* __restrict__ batch, float* __restrict__ pooled)
{
    extern __shared__ float smem[];
    float* sX = smem;
    float* sW = smem + TILE_ROWS * SX_STRIDE;

    const int tid = threadIdx.x;
    const int tc = tid & 15;
    const int tr = tid >> 4;
    const int row0 = blockIdx.x * TILE_ROWS;
    const float epsf = 1.0f + __ldg(&epsp[0]);

    LOAD_W_CHUNK(sW, W)
#pragma unroll
    for (int i = 0; i < 8; ++i) {
        int f4 = tid + i * NTHREADS;
        int r = f4 >> 4, c4 = f4 & 15;
        int row = row0 + r;
        float4 v = make_float4(0.f, 0.f, 0.f, 0.f);
        if (row < N_NODES) {
            size_t off = (size_t)row * 64 + c4 * 4;
            float4 a = *(const float4*)&A[off];
            float4 g = *(const float4*)&G[off];
            float4 pb = *(const float4*)&preb[c4 * 4];
            v.x = fmaxf(fmaf(epsf, a.x, g.x) + pb.x, 0.f);
            v.y = fmaxf(fmaf(epsf, a.y, g.y) + pb.y, 0.f);
            v.z = fmaxf(fmaf(epsf, a.z, g.z) + pb.z, 0.f);
            v.w = fmaxf(fmaf(epsf, a.w, g.w) + pb.w, 0.f);
        }
        *(float4*)&sX[r * SX_STRIDE + c4 * 4] = v;
    }
    __syncthreads();

    GEMM_ACC_DECL;
    GEMM_COMPUTE_CHUNK(sX, sW)

    const float4 bv = *(const float4*)&bias[tc * 4];
#pragma unroll
    for (int i = 0; i < 8; ++i) {
        int row = row0 + tr + 8 * i;
        if (row < N_NODES) {
            int g = __ldg(&batch[row]);
            float4 o;
            GEMM_UNPACK_ROW(i, o)
            o.x = fmaxf(o.x + bv.x, 0.f);
            o.y = fmaxf(o.y + bv.y, 0.f);
            o.z = fmaxf(o.z + bv.z, 0.f);
            o.w = fmaxf(o.w + bv.w, 0.f);
            float* p = pooled + (size_t)g * 64 + tc * 4;
            asm volatile("red.global.add.v4.f32 [%0], {%1,%2,%3,%4};"
                         :: "l"(p), "f"(o.x), "f"(o.y), "f"(o.z), "f"(o.w) : "memory");
        }
    }
}

// ============================================================================
// K7: head: logits + log_softmax
// ============================================================================
__global__ void __launch_bounds__(256) head_kernel(
    const float* __restrict__ pooled, const float* __restrict__ fcw,
    const float* __restrict__ fcb, float* __restrict__ out)
{
    int g = blockIdx.x * blockDim.x + threadIdx.x;
    if (g >= N_GRAPHS) return;
    float logit[OUT_CH];
#pragma unroll
    for (int j = 0; j < OUT_CH; ++j) logit[j] = __ldg(&fcb[j]);
#pragma unroll 8
    for (int k = 0; k < HID; ++k) {
        float p = pooled[g * HID + k];
#pragma unroll
        for (int j = 0; j < OUT_CH; ++j)
            logit[j] += p * __ldg(&fcw[k * OUT_CH + j]);
    }
    float m = logit[0];
#pragma unroll
    for (int j = 1; j < OUT_CH; ++j) m = fmaxf(m, logit[j]);
    float s = 0.f;
#pragma unroll
    for (int j = 0; j < OUT_CH; ++j) s += __expf(logit[j] - m);
    float ls = m + logf(s);
#pragma unroll
    for (int j = 0; j < OUT_CH; ++j) out[g * OUT_CH + j] = logit[j] - ls;
}

// ---------------- launch ----------------------------------------------------
extern "C" void kernel_launch(void* const* d_in, const int* in_sizes, int n_in,
                              void* d_out, int out_size)
{
    const float* x    = (const float*)d_in[0];
    const int*   ei   = (const int*)d_in[1];
    const int*   batch= (const int*)d_in[2];
    const float* eps0 = (const float*)d_in[3];
    const float* w0a  = (const float*)d_in[4];
    const float* b0a  = (const float*)d_in[5];
    const float* w0b  = (const float*)d_in[6];
    const float* b0b  = (const float*)d_in[7];
    const float* eps1 = (const float*)d_in[8];
    const float* w1a  = (const float*)d_in[9];
    const float* b1a  = (const float*)d_in[10];
    const float* w1b  = (const float*)d_in[11];
    const float* b1b  = (const float*)d_in[12];
    const float* fcw  = (const float*)d_in[13];
    const float* fcb  = (const float*)d_in[14];
    float*       out  = (float*)d_out;

    float *bufA, *bufB, *bufC, *pooled;
    cudaGetSymbolAddress((void**)&bufA, g_bufA);
    cudaGetSymbolAddress((void**)&bufB, g_bufB);
    cudaGetSymbolAddress((void**)&bufC, g_bufC);
    cudaGetSymbolAddress((void**)&pooled, g_pooled);

    static bool attr_done = false;
    if (!attr_done) {
        cudaFuncSetAttribute(gemm_in_kernel,
            cudaFuncAttributeMaxDynamicSharedMemorySize, SMEM_BYTES);
        cudaFuncSetAttribute(mlp_fuse_kernel,
            cudaFuncAttributeMaxDynamicSharedMemorySize, SMEM_BYTES);
        cudaFuncSetAttribute(combine_gemm_pool_kernel,
            cudaFuncAttributeMaxDynamicSharedMemorySize, SMEM_BYTES);
        attr_done = true;
    }

    const int gemm_blocks = (N_NODES + TILE_ROWS - 1) / TILE_ROWS;   // 782
    const int edge_blocks = (N_EDGES / E_PER * 16 + 255) / 256;      // 6250

    // K1: y0 = x @ w0a ; zero bufB + pooled
    gemm_in_kernel<<<gemm_blocks, NTHREADS, SMEM_BYTES>>>(x, w0a, bufA, bufB, pooled);
    // K2: agg0 = scatter-add(y0)
    edge_agg_kernel<<<edge_blocks, 256>>>(bufA, ei, bufB);
    // K3 (fused): y1 = relu(relu(combine0)@w0b+b0b) @ w1a -> bufC ; re-zero bufB in tail
    mlp_fuse_kernel<<<gemm_blocks, NTHREADS, SMEM_BYTES>>>(
        bufA, bufB, eps0, b0a, w0b, b0b, w1a, bufC, bufB);
    // K5: agg1 = scatter-add(y1)
    edge_agg_kernel<<<edge_blocks, 256>>>(bufC, ei, bufB);
    // K6: h1 = relu(relu(combine1) @ w1b + b1b) ; pool into pooled
    combine_gemm_pool_kernel<<<gemm_blocks, NTHREADS, SMEM_BYTES>>>(
        bufC, bufB, eps1, b1a, w1b, b1b, batch, pooled);
    // K7: logits + log_softmax
    head_kernel<<<2, 256>>>(pooled, fcw, fcb, out);
}

// round 17
// speedup vs baseline: 1.4147x; 1.0160x over previous
#include <cuda_runtime.h>
#include <cstdint>

#define N_NODES  50000
#define N_EDGES  800000
#define IN_CH    128
#define HID      64
#define N_GRAPHS 512
#define OUT_CH   10

#define TILE_ROWS 64
#define NTHREADS  128
#define SX_STRIDE 68                    // 16B-aligned, conflict-free for row-diff 1
#define SMEM_BYTES (TILE_ROWS * SX_STRIDE * 4 + 64 * 64 * 4)   // 33792

// ---------------- PDL primitives --------------------------------------------
#define PDL_TRIGGER()  asm volatile("griddepcontrol.launch_dependents;" ::: "memory")
#define PDL_WAIT()     asm volatile("griddepcontrol.wait;" ::: "memory")

// ---------------- scratch (static device memory; no allocations) ------------
__device__ float g_bufA[N_NODES * HID];   // y0
__device__ float g_bufB[N_NODES * HID];   // agg buffer (atomics target)
__device__ float g_bufC[N_NODES * HID];   // y1
__device__ float g_pooled[N_GRAPHS * HID];

// ---------------- packed f32x2 helpers --------------------------------------
#define FMA2(acc, a, b) \
    asm("fma.rn.f32x2 %0, %1, %2, %0;" : "+l"(acc) : "l"(a), "l"(b))
#define PACK2(out, x) \
    asm("mov.b64 %0, {%1, %1};" : "=l"(out) : "r"(__float_as_uint(x)))
#define UNPACK2(lo, hi, in) \
    asm("mov.b64 {%0, %1}, %2;" : "=r"(lo), "=r"(hi) : "l"(in))

// ============================================================================
// Shared GEMM core (64x64 tile, 128 threads, 8 rows x 4 cols per thread,
// accumulators as 8 x 2 packed f32x2 col-pairs -> fma.rn.f32x2)
// Thread t: cols [tc*4, tc*4+4), rows {tr + 8*i}, tc = t&15, tr = t>>4 (0..7).
// ============================================================================

#define GEMM_ACC_DECL  unsigned long long acc01[8] = {}, acc23[8] = {}
#define GEMM_ACC_ZERO                                                         \
    _Pragma("unroll")                                                         \
    for (int i = 0; i < 8; ++i) { acc01[i] = 0ull; acc23[i] = 0ull; }

#define GEMM_COMPUTE_CHUNK(sX, sW)                                            \
    _Pragma("unroll 4")                                                       \
    for (int k = 0; k < 64; k += 4) {                                         \
        ulonglong2 wv0 = *(const ulonglong2*)&sW[(k + 0) * 64 + tc * 4];      \
        ulonglong2 wv1 = *(const ulonglong2*)&sW[(k + 1) * 64 + tc * 4];      \
        ulonglong2 wv2 = *(const ulonglong2*)&sW[(k + 2) * 64 + tc * 4];      \
        ulonglong2 wv3 = *(const ulonglong2*)&sW[(k + 3) * 64 + tc * 4];      \
        _Pragma("unroll")                                                     \
        for (int i = 0; i < 8; ++i) {                                         \
            float4 xv = *(const float4*)&sX[(tr + 8 * i) * SX_STRIDE + k];    \
            unsigned long long xx;                                            \
            PACK2(xx, xv.x);                                                  \
            FMA2(acc01[i], xx, wv0.x); FMA2(acc23[i], xx, wv0.y);             \
            PACK2(xx, xv.y);                                                  \
            FMA2(acc01[i], xx, wv1.x); FMA2(acc23[i], xx, wv1.y);             \
            PACK2(xx, xv.z);                                                  \
            FMA2(acc01[i], xx, wv2.x); FMA2(acc23[i], xx, wv2.y);             \
            PACK2(xx, xv.w);                                                  \
            FMA2(acc01[i], xx, wv3.x); FMA2(acc23[i], xx, wv3.y);             \
        }                                                                     \
    }

#define GEMM_UNPACK_ROW(i, o)                                                 \
    {                                                                         \
        unsigned int u0, u1, u2, u3;                                          \
        UNPACK2(u0, u1, acc01[i]);                                            \
        UNPACK2(u2, u3, acc23[i]);                                            \
        o.x = __uint_as_float(u0); o.y = __uint_as_float(u1);                 \
        o.z = __uint_as_float(u2); o.w = __uint_as_float(u3);                 \
    }

#define LOAD_W_CHUNK(sW, Wptr)                                                \
    _Pragma("unroll")                                                         \
    for (int i = 0; i < 8; ++i) {                                             \
        int f4 = tid + i * NTHREADS;       /* 1024 float4s */                 \
        *(float4*)&sW[f4 * 4] = *(const float4*)&(Wptr)[f4 * 4];              \
    }

// ============================================================================
// K1: y0 = x @ w0a  (K=128). Tail: zero agg rows; block 0 zeroes pooled.
// Plain launch (zeroes pooled, read by previous replay's head kernel).
// ============================================================================
__global__ void __launch_bounds__(NTHREADS) gemm_in_kernel(
    const float* __restrict__ A, const float* __restrict__ W,
    float* __restrict__ out, float* __restrict__ aggz, float* __restrict__ pooled)
{
    extern __shared__ float smem[];
    float* sX = smem;
    float* sW = smem + TILE_ROWS * SX_STRIDE;

    PDL_TRIGGER();          // let K2 launch early and run its index prologue

    const int tid = threadIdx.x;
    const int tc = tid & 15;
    const int tr = tid >> 4;
    const int row0 = blockIdx.x * TILE_ROWS;

    GEMM_ACC_DECL;

    for (int kc = 0; kc < IN_CH; kc += 64) {
        LOAD_W_CHUNK(sW, W + kc * 64)
#pragma unroll
        for (int i = 0; i < 8; ++i) {
            int f4 = tid + i * NTHREADS;       // 1024 float4s = 64 rows x 16
            int r = f4 >> 4, c4 = f4 & 15;
            int row = row0 + r;
            float4 v = make_float4(0.f, 0.f, 0.f, 0.f);
            if (row < N_NODES)
                v = *(const float4*)&A[(size_t)row * IN_CH + kc + c4 * 4];
            *(float4*)&sX[r * SX_STRIDE + c4 * 4] = v;
        }
        __syncthreads();
        GEMM_COMPUTE_CHUNK(sX, sW)
        __syncthreads();
    }

#pragma unroll
    for (int i = 0; i < 8; ++i) {
        int row = row0 + tr + 8 * i;
        if (row < N_NODES) {
            float4 o;
            GEMM_UNPACK_ROW(i, o)
            *(float4*)&out[(size_t)row * 64 + tc * 4] = o;
        }
    }

    const float4 z4 = make_float4(0.f, 0.f, 0.f, 0.f);
#pragma unroll
    for (int i = 0; i < 8; ++i) {
        int f4 = tid + i * NTHREADS;
        int row = row0 + (f4 >> 4);
        if (row < N_NODES)
            *(float4*)&aggz[(size_t)row * 64 + (f4 & 15) * 4] = z4;
    }
    if (blockIdx.x == 0) {
        for (int i = tid; i < N_GRAPHS * HID / 4; i += NTHREADS)
            ((float4*)pooled)[i] = z4;
    }
}

// ============================================================================
// Edge aggregation (8 edges/thread, red.global.add.v4).
// PDL: independent index loads overlap the producer; wait before gather of y.
// ============================================================================
#define E_PER 8
__global__ void __launch_bounds__(256) edge_agg_kernel(
    const float* __restrict__ y, const int* __restrict__ ei,
    float* __restrict__ agg)
{
    PDL_TRIGGER();

    const int t = blockIdx.x * blockDim.x + threadIdx.x;
    const int c4 = t & 15;
    const int eb = (t >> 4) * E_PER;     // always < N_EDGES at this grid size

    int s[E_PER], d[E_PER];
#pragma unroll
    for (int j = 0; j < E_PER; ++j) {
        s[j] = __ldg(&ei[eb + j]);
        d[j] = __ldg(&ei[N_EDGES + eb + j]);
    }

    PDL_WAIT();                          // y must be complete

    float4 v[E_PER];
#pragma unroll
    for (int j = 0; j < E_PER; ++j)
        v[j] = *(const float4*)(y + (size_t)s[j] * 64 + c4 * 4);
#pragma unroll
    for (int j = 0; j < E_PER; ++j) {
        float* p = agg + (size_t)d[j] * 64 + c4 * 4;
        asm volatile("red.global.add.v4.f32 [%0], {%1,%2,%3,%4};"
                     :: "l"(p), "f"(v[j].x), "f"(v[j].y), "f"(v[j].z), "f"(v[j].w)
                     : "memory");
    }
}

// ============================================================================
// K3 (fused): T = relu( relu((1+eps)*A + G + preb) @ Wb + bb )   [smem only]
//             y1 = T @ Wn  -> out
// Tail: re-zero agg buffer rows. PDL: Wb load overlaps edge_agg.
// ============================================================================
__global__ void __launch_bounds__(NTHREADS) mlp_fuse_kernel(
    const float* __restrict__ A, const float* __restrict__ G,
    const float* __restrict__ epsp, const float* __restrict__ preb,
    const float* __restrict__ Wb, const float* __restrict__ bb,
    const float* __restrict__ Wn, float* __restrict__ out,
    float* __restrict__ aggz)
{
    extern __shared__ float smem[];
    float* sX = smem;
    float* sW = smem + TILE_ROWS * SX_STRIDE;

    PDL_TRIGGER();

    const int tid = threadIdx.x;
    const int tc = tid & 15;
    const int tr = tid >> 4;
    const int row0 = blockIdx.x * TILE_ROWS;
    const float epsf = 1.0f + __ldg(&epsp[0]);

    LOAD_W_CHUNK(sW, Wb)                 // independent prologue

    PDL_WAIT();                          // G (agg) must be complete

#pragma unroll
    for (int i = 0; i < 8; ++i) {
        int f4 = tid + i * NTHREADS;
        int r = f4 >> 4, c4 = f4 & 15;
        int row = row0 + r;
        float4 v = make_float4(0.f, 0.f, 0.f, 0.f);
        if (row < N_NODES) {
            size_t off = (size_t)row * 64 + c4 * 4;
            float4 a = *(const float4*)&A[off];
            float4 g = *(const float4*)&G[off];
            float4 pb = *(const float4*)&preb[c4 * 4];
            v.x = fmaxf(fmaf(epsf, a.x, g.x) + pb.x, 0.f);
            v.y = fmaxf(fmaf(epsf, a.y, g.y) + pb.y, 0.f);
            v.z = fmaxf(fmaf(epsf, a.z, g.z) + pb.z, 0.f);
            v.w = fmaxf(fmaf(epsf, a.w, g.w) + pb.w, 0.f);
        }
        *(float4*)&sX[r * SX_STRIDE + c4 * 4] = v;
    }
    __syncthreads();

    GEMM_ACC_DECL;
    GEMM_COMPUTE_CHUNK(sX, sW)
    __syncthreads();                       // all reads of sX/sW done

    {
        const float4 bv = *(const float4*)&bb[tc * 4];
#pragma unroll
        for (int i = 0; i < 8; ++i) {
            float4 o;
            GEMM_UNPACK_ROW(i, o)
            o.x = fmaxf(o.x + bv.x, 0.f);
            o.y = fmaxf(o.y + bv.y, 0.f);
            o.z = fmaxf(o.z + bv.z, 0.f);
            o.w = fmaxf(o.w + bv.w, 0.f);
            *(float4*)&sX[(tr + 8 * i) * SX_STRIDE + tc * 4] = o;
        }
    }
    LOAD_W_CHUNK(sW, Wn)
    __syncthreads();

    GEMM_ACC_ZERO
    GEMM_COMPUTE_CHUNK(sX, sW)

#pragma unroll
    for (int i = 0; i < 8; ++i) {
        int row = row0 + tr + 8 * i;
        if (row < N_NODES) {
            float4 o;
            GEMM_UNPACK_ROW(i, o)
            *(float4*)&out[(size_t)row * 64 + tc * 4] = o;
        }
    }

    const float4 z4 = make_float4(0.f, 0.f, 0.f, 0.f);
#pragma unroll
    for (int i = 0; i < 8; ++i) {
        int f4 = tid + i * NTHREADS;
        int row = row0 + (f4 >> 4);
        if (row < N_NODES)
            *(float4*)&aggz[(size_t)row * 64 + (f4 & 15) * 4] = z4;
    }
}

// ============================================================================
// K6: combine + GEMM + pool (h1 never hits global). PDL: W load overlaps agg1.
// ============================================================================
__global__ void __launch_bounds__(NTHREADS) combine_gemm_pool_kernel(
    const float* __restrict__ A, const float* __restrict__ G,
    const float* __restrict__ epsp, const float* __restrict__ preb,
    const float* __restrict__ W, const float* __restrict__ bias,
    const int* __restrict__ batch, float* __restrict__ pooled)
{
    extern __shared__ float smem[];
    float* sX = smem;
    float* sW = smem + TILE_ROWS * SX_STRIDE;

    PDL_TRIGGER();

    const int tid = threadIdx.x;
    const int tc = tid & 15;
    const int tr = tid >> 4;
    const int row0 = blockIdx.x * TILE_ROWS;
    const float epsf = 1.0f + __ldg(&epsp[0]);

    LOAD_W_CHUNK(sW, W)

    PDL_WAIT();                          // G (agg1) must be complete

#pragma unroll
    for (int i = 0; i < 8; ++i) {
        int f4 = tid + i * NTHREADS;
        int r = f4 >> 4, c4 = f4 & 15;
        int row = row0 + r;
        float4 v = make_float4(0.f, 0.f, 0.f, 0.f);
        if (row < N_NODES) {
            size_t off = (size_t)row * 64 + c4 * 4;
            float4 a = *(const float4*)&A[off];
            float4 g = *(const float4*)&G[off];
            float4 pb = *(const float4*)&preb[c4 * 4];
            v.x = fmaxf(fmaf(epsf, a.x, g.x) + pb.x, 0.f);
            v.y = fmaxf(fmaf(epsf, a.y, g.y) + pb.y, 0.f);
            v.z = fmaxf(fmaf(epsf, a.z, g.z) + pb.z, 0.f);
            v.w = fmaxf(fmaf(epsf, a.w, g.w) + pb.w, 0.f);
        }
        *(float4*)&sX[r * SX_STRIDE + c4 * 4] = v;
    }
    __syncthreads();

    GEMM_ACC_DECL;
    GEMM_COMPUTE_CHUNK(sX, sW)

    const float4 bv = *(const float4*)&bias[tc * 4];
#pragma unroll
    for (int i = 0; i < 8; ++i) {
        int row = row0 + tr + 8 * i;
        if (row < N_NODES) {
            int g = __ldg(&batch[row]);
            float4 o;
            GEMM_UNPACK_ROW(i, o)
            o.x = fmaxf(o.x + bv.x, 0.f);
            o.y = fmaxf(o.y + bv.y, 0.f);
            o.z = fmaxf(o.z + bv.z, 0.f);
            o.w = fmaxf(o.w + bv.w, 0.f);
            float* p = pooled + (size_t)g * 64 + tc * 4;
            asm volatile("red.global.add.v4.f32 [%0], {%1,%2,%3,%4};"
                         :: "l"(p), "f"(o.x), "f"(o.y), "f"(o.z), "f"(o.w) : "memory");
        }
    }
}

// ============================================================================
// K7: head: logits + log_softmax. PDL: waits for pooled.
// ============================================================================
__global__ void __launch_bounds__(256) head_kernel(
    const float* __restrict__ pooled, const float* __restrict__ fcw,
    const float* __restrict__ fcb, float* __restrict__ out)
{
    int g = blockIdx.x * blockDim.x + threadIdx.x;

    float logit[OUT_CH];
#pragma unroll
    for (int j = 0; j < OUT_CH; ++j) logit[j] = __ldg(&fcb[j]);   // independent

    PDL_WAIT();                          // pooled must be complete

    if (g >= N_GRAPHS) return;
#pragma unroll 8
    for (int k = 0; k < HID; ++k) {
        float p = pooled[g * HID + k];
#pragma unroll
        for (int j = 0; j < OUT_CH; ++j)
            logit[j] += p * __ldg(&fcw[k * OUT_CH + j]);
    }
    float m = logit[0];
#pragma unroll
    for (int j = 1; j < OUT_CH; ++j) m = fmaxf(m, logit[j]);
    float s = 0.f;
#pragma unroll
    for (int j = 0; j < OUT_CH; ++j) s += __expf(logit[j] - m);
    float ls = m + logf(s);
#pragma unroll
    for (int j = 0; j < OUT_CH; ++j) out[g * OUT_CH + j] = logit[j] - ls;
}

// ---------------- untyped PDL launch helper ----------------------------------
static void launch_pdl(void* kern, int grid, int nthreads, size_t smem,
                       void** args)
{
    cudaLaunchConfig_t cfg = {};
    cfg.gridDim = dim3((unsigned)grid, 1, 1);
    cfg.blockDim = dim3((unsigned)nthreads, 1, 1);
    cfg.dynamicSmemBytes = smem;
    cudaLaunchAttribute at[1];
    at[0].id = cudaLaunchAttributeProgrammaticStreamSerialization;
    at[0].val.programmaticStreamSerializationAllowed = 1;
    cfg.attrs = at;
    cfg.numAttrs = 1;
    cudaLaunchKernelExC(&cfg, kern, args);
}

extern "C" void kernel_launch(void* const* d_in, const int* in_sizes, int n_in,
                              void* d_out, int out_size)
{
    const float* x    = (const float*)d_in[0];
    const int*   ei   = (const int*)d_in[1];
    const int*   batch= (const int*)d_in[2];
    const float* eps0 = (const float*)d_in[3];
    const float* w0a  = (const float*)d_in[4];
    const float* b0a  = (const float*)d_in[5];
    const float* w0b  = (const float*)d_in[6];
    const float* b0b  = (const float*)d_in[7];
    const float* eps1 = (const float*)d_in[8];
    const float* w1a  = (const float*)d_in[9];
    const float* b1a  = (const float*)d_in[10];
    const float* w1b  = (const float*)d_in[11];
    const float* b1b  = (const float*)d_in[12];
    const float* fcw  = (const float*)d_in[13];
    const float* fcb  = (const float*)d_in[14];
    float*       out  = (float*)d_out;

    float *bufA, *bufB, *bufC, *pooled;
    cudaGetSymbolAddress((void**)&bufA, g_bufA);
    cudaGetSymbolAddress((void**)&bufB, g_bufB);
    cudaGetSymbolAddress((void**)&bufC, g_bufC);
    cudaGetSymbolAddress((void**)&pooled, g_pooled);

    static bool attr_done = false;
    if (!attr_done) {
        cudaFuncSetAttribute(gemm_in_kernel,
            cudaFuncAttributeMaxDynamicSharedMemorySize, SMEM_BYTES);
        cudaFuncSetAttribute(mlp_fuse_kernel,
            cudaFuncAttributeMaxDynamicSharedMemorySize, SMEM_BYTES);
        cudaFuncSetAttribute(combine_gemm_pool_kernel,
            cudaFuncAttributeMaxDynamicSharedMemorySize, SMEM_BYTES);
        attr_done = true;
    }

    const int gemm_blocks = (N_NODES + TILE_ROWS - 1) / TILE_ROWS;   // 782
    const int edge_blocks = (N_EDGES / E_PER * 16 + 255) / 256;      // 6250

    // K1: y0 = x @ w0a ; zero bufB + pooled (plain launch)
    gemm_in_kernel<<<gemm_blocks, NTHREADS, SMEM_BYTES>>>(x, w0a, bufA, bufB, pooled);

    // K2: agg0 = scatter-add(y0)  [PDL]
    {
        void* a0 = (void*)bufA; void* a1 = (void*)ei; void* a2 = (void*)bufB;
        void* args[3] = { &a0, &a1, &a2 };
        launch_pdl((void*)edge_agg_kernel, edge_blocks, 256, 0, args);
    }
    // K3 (fused): y1 = relu(relu(combine0)@w0b+b0b) @ w1a -> bufC ; re-zero bufB
    {
        void* a0 = (void*)bufA;  void* a1 = (void*)bufB; void* a2 = (void*)eps0;
        void* a3 = (void*)b0a;   void* a4 = (void*)w0b;  void* a5 = (void*)b0b;
        void* a6 = (void*)w1a;   void* a7 = (void*)bufC; void* a8 = (void*)bufB;
        void* args[9] = { &a0, &a1, &a2, &a3, &a4, &a5, &a6, &a7, &a8 };
        launch_pdl((void*)mlp_fuse_kernel, gemm_blocks, NTHREADS, SMEM_BYTES, args);
    }
    // K5: agg1 = scatter-add(y1)  [PDL]
    {
        void* a0 = (void*)bufC; void* a1 = (void*)ei; void* a2 = (void*)bufB;
        void* args[3] = { &a0, &a1, &a2 };
        launch_pdl((void*)edge_agg_kernel, edge_blocks, 256, 0, args);
    }
    // K6: h1 = relu(relu(combine1) @ w1b + b1b) ; pool into pooled  [PDL]
    {
        void* a0 = (void*)bufC;  void* a1 = (void*)bufB; void* a2 = (void*)eps1;
        void* a3 = (void*)b1a;   void* a4 = (void*)w1b;  void* a5 = (void*)b1b;
        void* a6 = (void*)batch; void* a7 = (void*)pooled;
        void* args[8] = { &a0, &a1, &a2, &a3, &a4, &a5, &a6, &a7 };
        launch_pdl((void*)combine_gemm_pool_kernel, gemm_blocks, NTHREADS, SMEM_BYTES, args);
    }
    // K7: logits + log_softmax  [PDL]
    {
        void* a0 = (void*)pooled; void* a1 = (void*)fcw;
        void* a2 = (void*)fcb;    void* a3 = (void*)out;
        void* args[4] = { &a0, &a1, &a2, &a3 };
        launch_pdl((void*)head_kernel, 2, 256, 0, args);
    }
}